// round 10
// baseline (speedup 1.0000x reference)
#include <cuda_runtime.h>
#include <cuda_bf16.h>
#include <math.h>

#define Vv 18000
#define Hh 400
#define Bb 16
#define TENC 256
#define Ss 30
#define TDEC 8
#define Gg 3
#define SB 480
#define H3 1200
#define PTR_OUT 69120000L

typedef unsigned long long ull;
typedef unsigned int u32;

// ---------------- scratch ----------------
#define OX    0L
#define OGI0  1638400L
#define OGI1  6553600L
#define OHF   11468800L
#define OHB   13107200L
#define OEO   14745600L
#define OEOT  16384000L
#define OH    18022400L
#define ODIN  18214400L
#define OGI   18406400L
#define OGH   18982400L
#define OPROB 19558400L
#define OCTX  19681280L
#define OSW   19873280L
#define ORSUM 19873760L
#define STOT  19874720L

__device__ float d_S[STOT];
__device__ float d_Hbuf[2][2][Bb * Hh];
__device__ unsigned g_barcnt[2], g_bargen[2];
// bf16 split operands for tensor-core GEMMs
__device__ __nv_bfloat16 d_ehi[(long)Vv * Hh];
__device__ __nv_bfloat16 d_elo[(long)Vv * Hh];
__device__ __nv_bfloat16 d_hhi[SB * Hh];
__device__ __nv_bfloat16 d_hlo[SB * Hh];
__device__ __nv_bfloat16 d_xhi[TENC * Bb * Hh];
__device__ __nv_bfloat16 d_xlo[TENC * Bb * Hh];
__device__ __nv_bfloat16 d_wfhi[H3 * Hh], d_wflo[H3 * Hh];
__device__ __nv_bfloat16 d_wbhi[H3 * Hh], d_wblo[H3 * Hh];

// ---------------- fast exp (FMA-only, rel err ~1e-7) ----------------
__device__ __forceinline__ float fexp(float x) {
    x = fminf(fmaxf(x, -80.0f), 80.0f);
    float y = x * 1.4426950408889634f;
    int   i = __float2int_rn(y);
    float f = y - (float)i;
    float u = f * 0.6931471805599453f;
    float p = 1.0f + u * (1.0f + u * (0.5f + u * (0.16666667f +
              u * (0.041666668f + u * (0.008333334f + u * 0.0013888889f)))));
    return __int_as_float(__float_as_int(p) + (i << 23));
}
__device__ __forceinline__ float fsig(float x) { return 1.0f / (1.0f + fexp(-x)); }

__device__ __forceinline__ void bsplit(float v, __nv_bfloat16& hi, __nv_bfloat16& lo) {
    hi = __float2bfloat16(v);
    lo = __float2bfloat16(v - __bfloat162float(hi));
}

// ---------------- mma.sync bf16 m16n8k16, fp32 accum ----------------
__device__ __forceinline__ void mma_bf16(float* c, const u32* a, const u32* b) {
    asm volatile(
        "mma.sync.aligned.m16n8k16.row.col.f32.bf16.bf16.f32 "
        "{%0,%1,%2,%3}, {%4,%5,%6,%7}, {%8,%9}, {%0,%1,%2,%3};"
        : "+f"(c[0]), "+f"(c[1]), "+f"(c[2]), "+f"(c[3])
        : "r"(a[0]), "r"(a[1]), "r"(a[2]), "r"(a[3]), "r"(b[0]), "r"(b[1]));
}

// ---------------- init ----------------
__global__ void k_init() {
    int tid = blockIdx.x * blockDim.x + threadIdx.x;
    if (tid == 0) {
        g_barcnt[0] = 0u; g_barcnt[1] = 0u;
        g_bargen[0] = 0u; g_bargen[1] = 0u;
    }
    for (int i = tid; i < 2 * 2 * Bb * Hh; i += gridDim.x * blockDim.x)
        ((float*)d_Hbuf)[i] = 0.0f;
}

// ---------------- one-time conversions ----------------
__global__ void k_embconv(const float* __restrict__ emb) {
    long idx = (long)blockIdx.x * blockDim.x + threadIdx.x;
    if (idx >= (long)Vv * Hh) return;
    bsplit(emb[idx], d_ehi[idx], d_elo[idx]);
}
__global__ void k_wsplit(const float* __restrict__ w, __nv_bfloat16* hi, __nv_bfloat16* lo, int n) {
    int idx = blockIdx.x * blockDim.x + threadIdx.x;
    if (idx >= n) return;
    bsplit(w[idx], hi[idx], lo[idx]);
}
__global__ void k_embed(const int* __restrict__ story) {
    long idx = (long)blockIdx.x * blockDim.x + threadIdx.x;
    if (idx >= (long)TENC * Bb * Hh) return;
    int h = (int)(idx % Hh);
    int tb = (int)(idx / Hh);
    int b = tb & 15, t = tb >> 4;
    long src = (long)story[b * TENC + t] * Hh + h;
    d_xhi[idx] = d_ehi[src];
    d_xlo[idx] = d_elo[src];
}

// ---------------- generic batched TN SGEMM (64x64x16) ----------------
__global__ void __launch_bounds__(256) k_sgemm(
    const float* __restrict__ A, int lda, long sA,
    const float* __restrict__ Bw, int ldb, long sB,
    const float* __restrict__ bias,
    float* __restrict__ C, int ldc, long sC,
    int M, int N, int K)
{
    A  += (long)blockIdx.z * sA;
    Bw += (long)blockIdx.z * sB;
    C  += (long)blockIdx.z * sC;
    __shared__ float As[16][68];
    __shared__ float Bs[16][68];
    int tid = threadIdx.x;
    int tx = tid & 15, ty = tid >> 4;
    int row0 = blockIdx.y * 64, col0 = blockIdx.x * 64;
    int lm = tid >> 2, lk = (tid & 3) << 2;
    float acc[4][4] = {{0.f}};

    for (int k0 = 0; k0 < K; k0 += 16) {
        float4 va = make_float4(0.f, 0.f, 0.f, 0.f);
        float4 vb = make_float4(0.f, 0.f, 0.f, 0.f);
        if (row0 + lm < M) va = *(const float4*)(A + (long)(row0 + lm) * lda + k0 + lk);
        if (col0 + lm < N) vb = *(const float4*)(Bw + (long)(col0 + lm) * ldb + k0 + lk);
        __syncthreads();
        As[lk][lm] = va.x; As[lk+1][lm] = va.y; As[lk+2][lm] = va.z; As[lk+3][lm] = va.w;
        Bs[lk][lm] = vb.x; Bs[lk+1][lm] = vb.y; Bs[lk+2][lm] = vb.z; Bs[lk+3][lm] = vb.w;
        __syncthreads();
#pragma unroll
        for (int kk = 0; kk < 16; kk++) {
            float4 a = *(const float4*)&As[kk][ty << 2];
            float4 b = *(const float4*)&Bs[kk][tx << 2];
            acc[0][0] += a.x*b.x; acc[0][1] += a.x*b.y; acc[0][2] += a.x*b.z; acc[0][3] += a.x*b.w;
            acc[1][0] += a.y*b.x; acc[1][1] += a.y*b.y; acc[1][2] += a.y*b.z; acc[1][3] += a.y*b.w;
            acc[2][0] += a.z*b.x; acc[2][1] += a.z*b.y; acc[2][2] += a.z*b.z; acc[2][3] += a.z*b.w;
            acc[3][0] += a.w*b.x; acc[3][1] += a.w*b.y; acc[3][2] += a.w*b.z; acc[3][3] += a.w*b.w;
        }
    }
#pragma unroll
    for (int i = 0; i < 4; i++) {
        int gm = row0 + (ty << 2) + i;
        if (gm >= M) continue;
#pragma unroll
        for (int j = 0; j < 4; j++) {
            int gn = col0 + (tx << 2) + j;
            if (gn >= N) continue;
            float v = acc[i][j];
            if (bias) v += __ldg(&bias[gn]);
            C[(long)gm * ldc + gn] = v;
        }
    }
}

// ---------------- fused decoder GRU GEMMs: z=0 din@dWi->GI, z=1 h@dWh->GH ----------------
__global__ void __launch_bounds__(256) k_decgemm(
    const float* __restrict__ A0, const float* __restrict__ A1,
    const float* __restrict__ B0, const float* __restrict__ B1,
    const float* __restrict__ bias0, const float* __restrict__ bias1,
    float* __restrict__ C0, float* __restrict__ C1)
{
    const float* A = blockIdx.z ? A1 : A0;
    const float* Bw = blockIdx.z ? B1 : B0;
    const float* bias = blockIdx.z ? bias1 : bias0;
    float* C = blockIdx.z ? C1 : C0;
    __shared__ float As[16][68];
    __shared__ float Bs[16][68];
    int tid = threadIdx.x;
    int tx = tid & 15, ty = tid >> 4;
    int row0 = blockIdx.y * 64, col0 = blockIdx.x * 64;
    int lm = tid >> 2, lk = (tid & 3) << 2;
    float acc[4][4] = {{0.f}};

    for (int k0 = 0; k0 < Hh; k0 += 16) {
        float4 va = make_float4(0.f, 0.f, 0.f, 0.f);
        float4 vb = make_float4(0.f, 0.f, 0.f, 0.f);
        if (row0 + lm < SB) va = *(const float4*)(A + (long)(row0 + lm) * Hh + k0 + lk);
        if (col0 + lm < H3) vb = *(const float4*)(Bw + (long)(col0 + lm) * Hh + k0 + lk);
        __syncthreads();
        As[lk][lm] = va.x; As[lk+1][lm] = va.y; As[lk+2][lm] = va.z; As[lk+3][lm] = va.w;
        Bs[lk][lm] = vb.x; Bs[lk+1][lm] = vb.y; Bs[lk+2][lm] = vb.z; Bs[lk+3][lm] = vb.w;
        __syncthreads();
#pragma unroll
        for (int kk = 0; kk < 16; kk++) {
            float4 a = *(const float4*)&As[kk][ty << 2];
            float4 b = *(const float4*)&Bs[kk][tx << 2];
            acc[0][0] += a.x*b.x; acc[0][1] += a.x*b.y; acc[0][2] += a.x*b.z; acc[0][3] += a.x*b.w;
            acc[1][0] += a.y*b.x; acc[1][1] += a.y*b.y; acc[1][2] += a.y*b.z; acc[1][3] += a.y*b.w;
            acc[2][0] += a.z*b.x; acc[2][1] += a.z*b.y; acc[2][2] += a.z*b.z; acc[2][3] += a.z*b.w;
            acc[3][0] += a.w*b.x; acc[3][1] += a.w*b.y; acc[3][2] += a.w*b.z; acc[3][3] += a.w*b.w;
        }
    }
#pragma unroll
    for (int i = 0; i < 4; i++) {
        int gm = row0 + (ty << 2) + i;
        if (gm >= SB) continue;
#pragma unroll
        for (int j = 0; j < 4; j++) {
            int gn = col0 + (tx << 2) + j;
            if (gn >= H3) continue;
            C[(long)gm * H3 + gn] = acc[i][j] + __ldg(&bias[gn]);
        }
    }
}

// ---------------- 128x128 split-bf16 tensor-core GEMM (register-prefetch pipelined) ----------------
__global__ void __launch_bounds__(256) k_mma128(
    const __nv_bfloat16* __restrict__ Ahi, const __nv_bfloat16* __restrict__ Alo,
    const __nv_bfloat16* __restrict__ Bhi, const __nv_bfloat16* __restrict__ Blo,
    const float* __restrict__ bias,
    float* __restrict__ C, long ldc,
    float* __restrict__ rowsum, int expmode,
    int M, int N, int K)
{
    __shared__ __nv_bfloat16 As[2][128][18];
    __shared__ __nv_bfloat16 Bs[2][128][18];
    int tid = threadIdx.x;
    int warp = tid >> 5, lane = tid & 31;
    int wm = warp >> 1, wn = warp & 1;
    int g = lane >> 2, tig = lane & 3;
    int m0 = blockIdx.y * 128, n0 = blockIdx.x * 128;

    // per-thread load slots (4 iterations x (A hi/lo, B hi/lo))
    int rowA[4], prA[4];
    bool vA[4], vB[4];
    long giA[4], giB[4];
#pragma unroll
    for (int it = 0; it < 4; it++) {
        int idx = it * 256 + tid;
        int row = idx >> 3, pr = idx & 7;
        rowA[it] = row; prA[it] = pr;
        int gm = m0 + row, gn = n0 + row;
        vA[it] = gm < M; vB[it] = gn < N;
        giA[it] = (long)gm * K + pr * 2;
        giB[it] = (long)gn * K + pr * 2;
    }

    u32 rah[4], ral[4], rbh[4], rbl[4];
#pragma unroll
    for (int it = 0; it < 4; it++) {
        rah[it] = vA[it] ? *(const u32*)(Ahi + giA[it]) : 0u;
        ral[it] = vA[it] ? *(const u32*)(Alo + giA[it]) : 0u;
        rbh[it] = vB[it] ? *(const u32*)(Bhi + giB[it]) : 0u;
        rbl[it] = vB[it] ? *(const u32*)(Blo + giB[it]) : 0u;
    }

    float c[2][8][4];
#pragma unroll
    for (int mt = 0; mt < 2; mt++)
#pragma unroll
        for (int s = 0; s < 8; s++)
#pragma unroll
            for (int q = 0; q < 4; q++) c[mt][s][q] = 0.f;

    int KT = K >> 4;
    for (int kt = 0; kt < KT; kt++) {
        // stage current chunk's registers into smem
#pragma unroll
        for (int it = 0; it < 4; it++) {
            *(u32*)&As[0][rowA[it]][prA[it] * 2] = rah[it];
            *(u32*)&As[1][rowA[it]][prA[it] * 2] = ral[it];
            *(u32*)&Bs[0][rowA[it]][prA[it] * 2] = rbh[it];
            *(u32*)&Bs[1][rowA[it]][prA[it] * 2] = rbl[it];
        }
        __syncthreads();

        // prefetch next chunk into registers (overlaps with MMA below)
        if (kt + 1 < KT) {
            long off = (long)(kt + 1) * 16;
#pragma unroll
            for (int it = 0; it < 4; it++) {
                rah[it] = vA[it] ? *(const u32*)(Ahi + giA[it] + off) : 0u;
                ral[it] = vA[it] ? *(const u32*)(Alo + giA[it] + off) : 0u;
                rbh[it] = vB[it] ? *(const u32*)(Bhi + giB[it] + off) : 0u;
                rbl[it] = vB[it] ? *(const u32*)(Blo + giB[it] + off) : 0u;
            }
        }

        u32 ah[2][4], al[2][4];
#pragma unroll
        for (int mt = 0; mt < 2; mt++) {
            int ar = wm * 32 + mt * 16 + g;
            ah[mt][0] = *(u32*)&As[0][ar][tig * 2];
            ah[mt][1] = *(u32*)&As[0][ar + 8][tig * 2];
            ah[mt][2] = *(u32*)&As[0][ar][tig * 2 + 8];
            ah[mt][3] = *(u32*)&As[0][ar + 8][tig * 2 + 8];
            al[mt][0] = *(u32*)&As[1][ar][tig * 2];
            al[mt][1] = *(u32*)&As[1][ar + 8][tig * 2];
            al[mt][2] = *(u32*)&As[1][ar][tig * 2 + 8];
            al[mt][3] = *(u32*)&As[1][ar + 8][tig * 2 + 8];
        }
#pragma unroll
        for (int sub = 0; sub < 8; sub++) {
            int bn = wn * 64 + sub * 8 + g;
            u32 bh[2], bl[2];
            bh[0] = *(u32*)&Bs[0][bn][tig * 2];
            bh[1] = *(u32*)&Bs[0][bn][tig * 2 + 8];
            bl[0] = *(u32*)&Bs[1][bn][tig * 2];
            bl[1] = *(u32*)&Bs[1][bn][tig * 2 + 8];
#pragma unroll
            for (int mt = 0; mt < 2; mt++) {
                mma_bf16(c[mt][sub], ah[mt], bh);   // hi*hi
                mma_bf16(c[mt][sub], ah[mt], bl);   // hi*lo
                mma_bf16(c[mt][sub], al[mt], bh);   // lo*hi
            }
        }
        __syncthreads();
    }

#pragma unroll
    for (int mt = 0; mt < 2; mt++) {
        int gmA = m0 + wm * 32 + mt * 16 + g;
        int gmB = gmA + 8;
        float sA = 0.f, sB = 0.f;
#pragma unroll
        for (int sub = 0; sub < 8; sub++) {
            int gn = n0 + wn * 64 + sub * 8 + tig * 2;
            if (gn < N) {
                float v0 = c[mt][sub][0], v1 = c[mt][sub][1];
                float v2 = c[mt][sub][2], v3 = c[mt][sub][3];
                if (bias) {
                    float b0 = __ldg(&bias[gn]), b1 = __ldg(&bias[gn + 1]);
                    v0 += b0; v1 += b1; v2 += b0; v3 += b1;
                }
                if (expmode) { v0 = fexp(v0); v1 = fexp(v1); v2 = fexp(v2); v3 = fexp(v3); }
                if (gmA < M) *(float2*)(C + (long)gmA * ldc + gn) = make_float2(v0, v1);
                if (gmB < M) *(float2*)(C + (long)gmB * ldc + gn) = make_float2(v2, v3);
                sA += v0 + v1; sB += v2 + v3;
            }
        }
        if (rowsum) {
            sA += __shfl_xor_sync(0xffffffffu, sA, 1);
            sA += __shfl_xor_sync(0xffffffffu, sA, 2);
            sB += __shfl_xor_sync(0xffffffffu, sB, 1);
            sB += __shfl_xor_sync(0xffffffffu, sB, 2);
            if (tig == 0) {
                if (gmA < M) atomicAdd(rowsum + gmA, sA);
                if (gmB < M) atomicAdd(rowsum + gmB, sB);
            }
        }
    }
}

// ---------------- persistent bi-GRU encoder ----------------
__global__ void __launch_bounds__(384, 1) k_enc(
    const float* __restrict__ Whh_f, const float* __restrict__ Whh_b,
    const float* __restrict__ bhh_f, const float* __restrict__ bhh_b)
{
    __shared__ float hs[16 * 404];
    __shared__ float ghs[24 * 16];
    __shared__ float bsh[24];

    int dir = (int)(blockIdx.x / 50);
    int jb  = (int)(blockIdx.x % 50);
    int j0  = jb * 8;
    const float* Whh = dir ? Whh_b : Whh_f;
    const float* bhh = dir ? bhh_b : bhh_f;
    const float* GI  = d_S + (dir ? OGI1 : OGI0);
    float* OUT = d_S + (dir ? OHB : OHF);
    int tid = threadIdx.x;

    int kp = tid & 15;
    int rgi = (tid >> 4) & 3;
    int qg = tid >> 6;
    int kbase = kp * 25;

    if (tid < 24) { int gate = tid >> 3, jl = tid & 7; bsh[tid] = bhh[gate * 400 + j0 + jl]; }

    float Wreg[4][25];
#pragma unroll
    for (int i = 0; i < 4; i++) {
        int q = qg * 4 + i;
        int gate = q >> 3, jl = q & 7;
        const float* wr = Whh + (long)(gate * 400 + j0 + jl) * 400 + kbase;
#pragma unroll
        for (int kk = 0; kk < 25; kk++) Wreg[i][kk] = wr[kk];
    }
    __syncthreads();

    for (int t = 0; t < TENC; ++t) {
        int p = t & 1;
        const float4* Hin4 = (const float4*)d_Hbuf[dir][p];
        float* Hout = d_Hbuf[dir][p ^ 1];

        float ir = 0.f, iz = 0.f, ig = 0.f;
        int time = dir ? (TENC - 1 - t) : t;
        if (tid < 128) {
            int rr = tid & 15, jj = tid >> 4;
            long gib = ((long)time * Bb + rr) * H3 + j0 + jj;
            ir = GI[gib]; iz = GI[gib + 400]; ig = GI[gib + 800];
        }

        for (int i4 = tid; i4 < 1600; i4 += 384) {
            float4 v = __ldcg(Hin4 + i4);
            int row = i4 / 100, c4 = (i4 % 100) << 2;
            *(float4*)&hs[row * 404 + c4] = v;
        }
        __syncthreads();

        float acc[4][4];
#pragma unroll
        for (int i = 0; i < 4; i++)
#pragma unroll
            for (int j = 0; j < 4; j++) acc[i][j] = 0.f;

        const float* h0 = hs + (rgi * 4 + 0) * 404 + kbase;
        const float* h1 = hs + (rgi * 4 + 1) * 404 + kbase;
        const float* h2 = hs + (rgi * 4 + 2) * 404 + kbase;
        const float* h3 = hs + (rgi * 4 + 3) * 404 + kbase;
#pragma unroll
        for (int kk = 0; kk < 25; kk++) {
            float hv0 = h0[kk], hv1 = h1[kk], hv2 = h2[kk], hv3 = h3[kk];
#pragma unroll
            for (int i = 0; i < 4; i++) {
                float w = Wreg[i][kk];
                acc[i][0] += w * hv0;
                acc[i][1] += w * hv1;
                acc[i][2] += w * hv2;
                acc[i][3] += w * hv3;
            }
        }

#pragma unroll
        for (int i = 0; i < 4; i++)
#pragma unroll
            for (int j = 0; j < 4; j++) {
                float v = acc[i][j];
                v += __shfl_xor_sync(0xffffffffu, v, 1);
                v += __shfl_xor_sync(0xffffffffu, v, 2);
                v += __shfl_xor_sync(0xffffffffu, v, 4);
                v += __shfl_xor_sync(0xffffffffu, v, 8);
                acc[i][j] = v;
            }
        if (kp == 0) {
#pragma unroll
            for (int i = 0; i < 4; i++) {
                float bb = bsh[qg * 4 + i];
#pragma unroll
                for (int j = 0; j < 4; j++)
                    ghs[(qg * 4 + i) * 16 + (rgi * 4 + j)] = acc[i][j] + bb;
            }
        }
        __syncthreads();

        if (tid < 128) {
            int rr = tid & 15, jj = tid >> 4;
            float hr_ = ghs[jj * 16 + rr];
            float hz_ = ghs[(8 + jj) * 16 + rr];
            float hg_ = ghs[(16 + jj) * 16 + rr];
            float hp  = hs[rr * 404 + j0 + jj];
            float rg_ = fsig(ir + hr_);
            float zg = fsig(iz + hz_);
            float gg = tanhf(ig + rg_ * hg_);
            float hn = (1.f - zg) * gg + zg * hp;
            Hout[rr * 400 + j0 + jj] = hn;
            OUT[((long)time * Bb + rr) * Hh + j0 + jj] = hn;
        }
        __syncthreads();
        if (tid == 0) {
            __threadfence();
            unsigned a = atomicAdd(&g_barcnt[dir], 1u);
            if (a == 50u * (unsigned)(t + 1) - 1u) {
                atomicAdd(&g_bargen[dir], 1u);
            } else {
                while (__ldcg((const unsigned*)&g_bargen[dir]) < (unsigned)(t + 1)) { __nanosleep(32); }
            }
            __threadfence();
        }
        __syncthreads();
    }
}

// ---------------- enc_out (B,T,H) and its transpose (B,H,T) ----------------
__global__ void k_encout() {
    long idx = (long)blockIdx.x * blockDim.x + threadIdx.x;
    if (idx >= (long)Bb * TENC * Hh) return;
    int b = (int)(idx / (TENC * Hh));
    int rem = (int)(idx % (TENC * Hh));
    int t = rem / Hh, h = rem % Hh;
    long src = ((long)t * Bb + b) * Hh + h;
    float v = d_S[OHF + src] + d_S[OHB + src];
    d_S[OEO + idx] = v;
    d_S[OEOT + (long)b * (Hh * TENC) + (long)h * TENC + t] = v;
}

// ---------------- decoder init ----------------
__global__ void k_dec_init(const float* __restrict__ slot) {
    int idx = blockIdx.x * blockDim.x + threadIdx.x;
    if (idx >= SB * Hh) return;
    int n = idx / Hh, h = idx % Hh;
    int s = n >> 4, b = n & 15;
    d_S[OH + idx]   = d_S[OHF + ((long)(TENC - 1) * Bb + b) * Hh + h]
                    + d_S[OHB + ((long)b) * Hh + h];
    d_S[ODIN + idx] = slot[s * Hh + h];
}

// ---------------- decoder GRU gates; zero rowsum + bf16 split of h ----------------
__global__ void k_dec_gates() {
    int idx = blockIdx.x * blockDim.x + threadIdx.x;
    if (idx < SB) d_S[ORSUM + idx] = 0.f;
    if (idx >= SB * Hh) return;
    int n = idx / Hh, j = idx % Hh;
    long gb = (long)n * H3 + j;
    float ir = d_S[OGI + gb], iz = d_S[OGI + gb + 400], ig = d_S[OGI + gb + 800];
    float hr = d_S[OGH + gb], hz = d_S[OGH + gb + 400], hg = d_S[OGH + gb + 800];
    float hp = d_S[OH + idx];
    float r = fsig(ir + hr);
    float z = fsig(iz + hz);
    float g = tanhf(ig + r * hg);
    float hn = (1.f - z) * g + z * hp;
    d_S[OH + idx] = hn;
    bsplit(hn, d_hhi[idx], d_hlo[idx]);
}

// ---------------- attention softmax over T=256 ----------------
__global__ void k_softmax_att() {
    int n = blockIdx.x, tid = threadIdx.x;
    __shared__ float red[256];
    float x = d_S[OPROB + (long)n * TENC + tid];
    red[tid] = x; __syncthreads();
    for (int o = 128; o; o >>= 1) { if (tid < o) red[tid] = fmaxf(red[tid], red[tid + o]); __syncthreads(); }
    float m = red[0]; __syncthreads();
    float e = fexp(x - m);
    red[tid] = e; __syncthreads();
    for (int o = 128; o; o >>= 1) { if (tid < o) red[tid] += red[tid + o]; __syncthreads(); }
    d_S[OPROB + (long)n * TENC + tid] = e / red[0];
}

// ---------------- sw (p_gen ratio) and (t==0) gate outputs ----------------
__global__ void k_sw_gate(const float* __restrict__ Wr, const float* __restrict__ br,
                          const float* __restrict__ Wg, const float* __restrict__ bg,
                          float* __restrict__ out, int t) {
    int warp = (blockIdx.x * blockDim.x + threadIdx.x) >> 5;
    int lane = threadIdx.x & 31;
    if (warp >= SB) return;
    int n = warp;
    float s = 0.f;
    for (int j = lane; j < H3; j += 32) {
        float v = (j < 400) ? d_S[OH + (long)n * Hh + j]
                : (j < 800) ? d_S[OCTX + (long)n * Hh + j - 400]
                            : d_S[ODIN + (long)n * Hh + j - 800];
        s += v * Wr[j];
    }
    for (int o = 16; o; o >>= 1) s += __shfl_xor_sync(0xffffffffu, s, o);
    if (lane == 0) d_S[OSW + n] = fsig(s + br[0]);
    if (t == 0) {
        for (int g = 0; g < Gg; g++) {
            float a = 0.f;
            for (int j = lane; j < Hh; j += 32) a += d_S[OCTX + (long)n * Hh + j] * Wg[g * Hh + j];
            for (int o = 16; o; o >>= 1) a += __shfl_xor_sync(0xffffffffu, a, o);
            if (lane == 0) out[PTR_OUT + (long)n * Gg + g] = a + bg[g];
        }
    }
}

// ---------------- scale out in place: *= sw/rowsum ----------------
__global__ void k_final(float* __restrict__ out, int t) {
    long idx = (long)blockIdx.x * blockDim.x + threadIdx.x;
    if (idx >= (long)SB * (Vv / 4)) return;
    int n = (int)(idx / (Vv / 4));
    int c = (int)(idx % (Vv / 4)) * 4;
    float sc = d_S[OSW + n] / d_S[ORSUM + n];
    float* p = out + ((long)n * TDEC + t) * Vv + c;
    float4 e = *(const float4*)p;
    e.x *= sc; e.y *= sc; e.z *= sc; e.w *= sc;
    *(float4*)p = e;
}

// ---------------- scatter-add pointer distribution ----------------
__global__ void k_scatter(float* __restrict__ out, const int* __restrict__ story, int t) {
    int idx = blockIdx.x * blockDim.x + threadIdx.x;
    if (idx >= SB * TENC) return;
    int n = idx >> 8, tt = idx & 255;
    int b = n & 15;
    int tok = story[b * TENC + tt];
    float v = (1.f - d_S[OSW + n]) * d_S[OPROB + (long)n * TENC + tt];
    atomicAdd(out + ((long)n * TDEC + t) * Vv + tok, v);
}

// ---------------- next decoder input ----------------
__global__ void k_next_din(const int* __restrict__ tb, const float* __restrict__ emb, int t) {
    int idx = blockIdx.x * blockDim.x + threadIdx.x;
    if (idx >= SB * Hh) return;
    int n = idx / Hh, h = idx % Hh;
    int s = n >> 4, b = n & 15;
    int tok = tb[(b * Ss + s) * TDEC + t];
    d_S[ODIN + idx] = emb[(long)tok * Hh + h];
}

// ---------------- host ----------------
extern "C" void kernel_launch(void* const* d_in, const int* in_sizes, int n_in,
                              void* d_out, int out_size) {
    const int*   story = (const int*)d_in[0];
    const int*   tb    = (const int*)d_in[1];
    const float* emb   = (const float*)d_in[2];
    const float* eWif  = (const float*)d_in[3];
    const float* eWhf  = (const float*)d_in[4];
    const float* ebif  = (const float*)d_in[5];
    const float* ebhf  = (const float*)d_in[6];
    const float* eWib  = (const float*)d_in[7];
    const float* eWhb  = (const float*)d_in[8];
    const float* ebib  = (const float*)d_in[9];
    const float* ebhb  = (const float*)d_in[10];
    const float* dWi   = (const float*)d_in[11];
    const float* dWh   = (const float*)d_in[12];
    const float* dbi   = (const float*)d_in[13];
    const float* dbh   = (const float*)d_in[14];
    const float* Wr    = (const float*)d_in[15];
    const float* br    = (const float*)d_in[16];
    const float* Wg    = (const float*)d_in[17];
    const float* bg    = (const float*)d_in[18];
    const float* slot  = (const float*)d_in[19];
    float* out = (float*)d_out;

    float* S = nullptr;
    cudaGetSymbolAddress((void**)&S, d_S);
    float* pGI0  = S + OGI0;
    float* pGI1  = S + OGI1;
    float* pEO   = S + OEO;
    float* pEOT  = S + OEOT;
    float* pH    = S + OH;
    float* pDIN  = S + ODIN;
    float* pGI   = S + OGI;
    float* pGH   = S + OGH;
    float* pPROB = S + OPROB;
    float* pCTX  = S + OCTX;
    float* pRS   = S + ORSUM;

    __nv_bfloat16 *xhi, *xlo, *wfhi, *wflo, *wbhi, *wblo, *ehi, *elo, *hhi, *hlo;
    cudaGetSymbolAddress((void**)&xhi, d_xhi);
    cudaGetSymbolAddress((void**)&xlo, d_xlo);
    cudaGetSymbolAddress((void**)&wfhi, d_wfhi);
    cudaGetSymbolAddress((void**)&wflo, d_wflo);
    cudaGetSymbolAddress((void**)&wbhi, d_wbhi);
    cudaGetSymbolAddress((void**)&wblo, d_wblo);
    cudaGetSymbolAddress((void**)&ehi, d_ehi);
    cudaGetSymbolAddress((void**)&elo, d_elo);
    cudaGetSymbolAddress((void**)&hhi, d_hhi);
    cudaGetSymbolAddress((void**)&hlo, d_hlo);

    k_init<<<32, 256>>>();
    k_embconv<<<(int)(((long)Vv * Hh + 255) / 256), 256>>>(emb);
    k_embed<<<(TENC * Bb * Hh + 255) / 256, 256>>>(story);
    k_wsplit<<<(H3 * Hh + 255) / 256, 256>>>(eWif, wfhi, wflo, H3 * Hh);
    k_wsplit<<<(H3 * Hh + 255) / 256, 256>>>(eWib, wbhi, wblo, H3 * Hh);

    // GI via tensor cores: (4096 x 1200 x 400)
    k_mma128<<<dim3(10, 32), 256>>>(xhi, xlo, wfhi, wflo, ebif, pGI0, H3, nullptr, 0, TENC * Bb, H3, Hh);
    k_mma128<<<dim3(10, 32), 256>>>(xhi, xlo, wbhi, wblo, ebib, pGI1, H3, nullptr, 0, TENC * Bb, H3, Hh);

    // persistent bidirectional GRU
    k_enc<<<100, 384>>>(eWhf, eWhb, ebhf, ebhb);

    k_encout<<<(Bb * TENC * Hh + 255) / 256, 256>>>();
    k_dec_init<<<(SB * Hh + 255) / 256, 256>>>(slot);

    for (int t = 0; t < TDEC; t++) {
        // fused GRU GEMMs (z=0: din@dWi -> GI, z=1: h@dWh -> GH)
        k_decgemm<<<dim3(19, 8, 2), 256>>>(pDIN, pH, dWi, dWh, dbi, dbh, pGI, pGH);
        k_dec_gates<<<(SB * Hh + 255) / 256, 256>>>();

        k_sgemm<<<dim3(4, 1, Bb), 256>>>(pH, Bb * Hh, Hh, pEO, Hh, (long)TENC * Hh,
                                         nullptr, pPROB, Bb * TENC, TENC, Ss, TENC, Hh);
        k_softmax_att<<<SB, 256>>>();
        k_sgemm<<<dim3(7, 1, Bb), 256>>>(pPROB, Bb * TENC, TENC, pEOT, TENC, (long)Hh * TENC,
                                         nullptr, pCTX, Bb * Hh, Hh, Ss, Hh, TENC);

        k_sw_gate<<<60, 256>>>(Wr, br, Wg, bg, out, t);

        // pipelined tensor-core logits: exp(logit) straight into out + rowsum
        k_mma128<<<dim3(141, 4), 256>>>(hhi, hlo, ehi, elo, nullptr,
                                        out + (long)t * Vv, (long)TDEC * Vv, pRS, 1, SB, Vv, Hh);
        k_final<<<(SB * (Vv / 4) + 255) / 256, 256>>>(out, t);
        k_scatter<<<SB, 256>>>(out, story, t);

        k_next_din<<<(SB * Hh + 255) / 256, 256>>>(tb, emb, t);
    }
}

// round 11
// speedup vs baseline: 1.0699x; 1.0699x over previous
#include <cuda_runtime.h>
#include <cuda_bf16.h>
#include <math.h>

#define Vv 18000
#define Hh 400
#define Bb 16
#define TENC 256
#define Ss 30
#define TDEC 8
#define Gg 3
#define SB 480
#define H3 1200
#define PTR_OUT 69120000L

typedef unsigned long long ull;
typedef unsigned int u32;

// ---------------- scratch ----------------
#define OGI0  1638400L
#define OGI1  6553600L
#define OHF   11468800L
#define OHB   13107200L
#define OEO   14745600L
#define OEOT  16384000L
#define OH    18022400L
#define ODIN  18214400L
#define OGI   18406400L
#define OGH   18982400L
#define OPROB 19558400L
#define OCTX  19681280L
#define OSW   19873280L
#define ORSUM 19873760L
#define STOT  19874720L

__device__ float d_S[STOT];
__device__ float d_Hbuf[2][2][Bb * Hh];
__device__ unsigned g_barcnt[2], g_bargen[2];
__device__ __nv_bfloat16 d_ehi[(long)Vv * Hh];
__device__ __nv_bfloat16 d_elo[(long)Vv * Hh];
__device__ __nv_bfloat16 d_hhi[SB * Hh];
__device__ __nv_bfloat16 d_hlo[SB * Hh];
__device__ __nv_bfloat16 d_xhi[TENC * Bb * Hh];
__device__ __nv_bfloat16 d_xlo[TENC * Bb * Hh];
__device__ __nv_bfloat16 d_wfhi[H3 * Hh], d_wflo[H3 * Hh];
__device__ __nv_bfloat16 d_wbhi[H3 * Hh], d_wblo[H3 * Hh];

// ---------------- packed f32x2 helpers ----------------
__device__ __forceinline__ ull pack2(float x, float y) {
    ull r; asm("mov.b64 %0, {%1, %2};" : "=l"(r) : "f"(x), "f"(y)); return r;
}
__device__ __forceinline__ void unpack2(ull v, float& x, float& y) {
    asm("mov.b64 {%0, %1}, %2;" : "=f"(x), "=f"(y) : "l"(v));
}
__device__ __forceinline__ void ffma2(ull& d, ull a, ull b) {
    asm("fma.rn.f32x2 %0, %1, %2, %3;" : "=l"(d) : "l"(a), "l"(b), "l"(d));
}

// ---------------- fast exp (FMA-only, rel err ~1e-7) ----------------
__device__ __forceinline__ float fexp(float x) {
    x = fminf(fmaxf(x, -80.0f), 80.0f);
    float y = x * 1.4426950408889634f;
    int   i = __float2int_rn(y);
    float f = y - (float)i;
    float u = f * 0.6931471805599453f;
    float p = 1.0f + u * (1.0f + u * (0.5f + u * (0.16666667f +
              u * (0.041666668f + u * (0.008333334f + u * 0.0013888889f)))));
    return __int_as_float(__float_as_int(p) + (i << 23));
}
__device__ __forceinline__ float fsig(float x) { return 1.0f / (1.0f + fexp(-x)); }

__device__ __forceinline__ void bsplit(float v, __nv_bfloat16& hi, __nv_bfloat16& lo) {
    hi = __float2bfloat16(v);
    lo = __float2bfloat16(v - __bfloat162float(hi));
}

// ---------------- mma.sync bf16 m16n8k16, fp32 accum ----------------
__device__ __forceinline__ void mma_bf16(float* c, const u32* a, const u32* b) {
    asm volatile(
        "mma.sync.aligned.m16n8k16.row.col.f32.bf16.bf16.f32 "
        "{%0,%1,%2,%3}, {%4,%5,%6,%7}, {%8,%9}, {%0,%1,%2,%3};"
        : "+f"(c[0]), "+f"(c[1]), "+f"(c[2]), "+f"(c[3])
        : "r"(a[0]), "r"(a[1]), "r"(a[2]), "r"(a[3]), "r"(b[0]), "r"(b[1]));
}

// ---------------- init ----------------
__global__ void k_init() {
    int tid = blockIdx.x * blockDim.x + threadIdx.x;
    if (tid == 0) {
        g_barcnt[0] = 0u; g_barcnt[1] = 0u;
        g_bargen[0] = 0u; g_bargen[1] = 0u;
    }
    for (int i = tid; i < 2 * 2 * Bb * Hh; i += gridDim.x * blockDim.x)
        ((float*)d_Hbuf)[i] = 0.0f;
}

// ---------------- one-time conversions ----------------
__global__ void k_embconv(const float* __restrict__ emb) {
    long idx = (long)blockIdx.x * blockDim.x + threadIdx.x;
    if (idx >= (long)Vv * Hh) return;
    bsplit(emb[idx], d_ehi[idx], d_elo[idx]);
}
__global__ void k_wsplit(const float* __restrict__ w, __nv_bfloat16* hi, __nv_bfloat16* lo, int n) {
    int idx = blockIdx.x * blockDim.x + threadIdx.x;
    if (idx >= n) return;
    bsplit(w[idx], hi[idx], lo[idx]);
}
__global__ void k_embed(const int* __restrict__ story) {
    long idx = (long)blockIdx.x * blockDim.x + threadIdx.x;
    if (idx >= (long)TENC * Bb * Hh) return;
    int h = (int)(idx % Hh);
    int tb = (int)(idx / Hh);
    int b = tb & 15, t = tb >> 4;
    long src = (long)story[b * TENC + t] * Hh + h;
    d_xhi[idx] = d_ehi[src];
    d_xlo[idx] = d_elo[src];
}

// ---------------- generic batched TN SGEMM (64x64x16) ----------------
__global__ void __launch_bounds__(256) k_sgemm(
    const float* __restrict__ A, int lda, long sA,
    const float* __restrict__ Bw, int ldb, long sB,
    const float* __restrict__ bias,
    float* __restrict__ C, int ldc, long sC,
    int M, int N, int K)
{
    A  += (long)blockIdx.z * sA;
    Bw += (long)blockIdx.z * sB;
    C  += (long)blockIdx.z * sC;
    __shared__ float As[16][68];
    __shared__ float Bs[16][68];
    int tid = threadIdx.x;
    int tx = tid & 15, ty = tid >> 4;
    int row0 = blockIdx.y * 64, col0 = blockIdx.x * 64;
    int lm = tid >> 2, lk = (tid & 3) << 2;
    float acc[4][4] = {{0.f}};

    for (int k0 = 0; k0 < K; k0 += 16) {
        float4 va = make_float4(0.f, 0.f, 0.f, 0.f);
        float4 vb = make_float4(0.f, 0.f, 0.f, 0.f);
        if (row0 + lm < M) va = *(const float4*)(A + (long)(row0 + lm) * lda + k0 + lk);
        if (col0 + lm < N) vb = *(const float4*)(Bw + (long)(col0 + lm) * ldb + k0 + lk);
        __syncthreads();
        As[lk][lm] = va.x; As[lk+1][lm] = va.y; As[lk+2][lm] = va.z; As[lk+3][lm] = va.w;
        Bs[lk][lm] = vb.x; Bs[lk+1][lm] = vb.y; Bs[lk+2][lm] = vb.z; Bs[lk+3][lm] = vb.w;
        __syncthreads();
#pragma unroll
        for (int kk = 0; kk < 16; kk++) {
            float4 a = *(const float4*)&As[kk][ty << 2];
            float4 b = *(const float4*)&Bs[kk][tx << 2];
            acc[0][0] += a.x*b.x; acc[0][1] += a.x*b.y; acc[0][2] += a.x*b.z; acc[0][3] += a.x*b.w;
            acc[1][0] += a.y*b.x; acc[1][1] += a.y*b.y; acc[1][2] += a.y*b.z; acc[1][3] += a.y*b.w;
            acc[2][0] += a.z*b.x; acc[2][1] += a.z*b.y; acc[2][2] += a.z*b.z; acc[2][3] += a.z*b.w;
            acc[3][0] += a.w*b.x; acc[3][1] += a.w*b.y; acc[3][2] += a.w*b.z; acc[3][3] += a.w*b.w;
        }
    }
#pragma unroll
    for (int i = 0; i < 4; i++) {
        int gm = row0 + (ty << 2) + i;
        if (gm >= M) continue;
#pragma unroll
        for (int j = 0; j < 4; j++) {
            int gn = col0 + (tx << 2) + j;
            if (gn >= N) continue;
            float v = acc[i][j];
            if (bias) v += __ldg(&bias[gn]);
            C[(long)gm * ldc + gn] = v;
        }
    }
}

// ---------------- fused decoder GRU GEMMs: z=0 din@dWi->GI, z=1 h@dWh->GH ----------------
__global__ void __launch_bounds__(256) k_decgemm(
    const float* __restrict__ A0, const float* __restrict__ A1,
    const float* __restrict__ B0, const float* __restrict__ B1,
    const float* __restrict__ bias0, const float* __restrict__ bias1,
    float* __restrict__ C0, float* __restrict__ C1)
{
    const float* A = blockIdx.z ? A1 : A0;
    const float* Bw = blockIdx.z ? B1 : B0;
    const float* bias = blockIdx.z ? bias1 : bias0;
    float* C = blockIdx.z ? C1 : C0;
    __shared__ float As[16][68];
    __shared__ float Bs[16][68];
    int tid = threadIdx.x;
    int tx = tid & 15, ty = tid >> 4;
    int row0 = blockIdx.y * 64, col0 = blockIdx.x * 64;
    int lm = tid >> 2, lk = (tid & 3) << 2;
    float acc[4][4] = {{0.f}};

    for (int k0 = 0; k0 < Hh; k0 += 16) {
        float4 va = make_float4(0.f, 0.f, 0.f, 0.f);
        float4 vb = make_float4(0.f, 0.f, 0.f, 0.f);
        if (row0 + lm < SB) va = *(const float4*)(A + (long)(row0 + lm) * Hh + k0 + lk);
        if (col0 + lm < H3) vb = *(const float4*)(Bw + (long)(col0 + lm) * Hh + k0 + lk);
        __syncthreads();
        As[lk][lm] = va.x; As[lk+1][lm] = va.y; As[lk+2][lm] = va.z; As[lk+3][lm] = va.w;
        Bs[lk][lm] = vb.x; Bs[lk+1][lm] = vb.y; Bs[lk+2][lm] = vb.z; Bs[lk+3][lm] = vb.w;
        __syncthreads();
#pragma unroll
        for (int kk = 0; kk < 16; kk++) {
            float4 a = *(const float4*)&As[kk][ty << 2];
            float4 b = *(const float4*)&Bs[kk][tx << 2];
            acc[0][0] += a.x*b.x; acc[0][1] += a.x*b.y; acc[0][2] += a.x*b.z; acc[0][3] += a.x*b.w;
            acc[1][0] += a.y*b.x; acc[1][1] += a.y*b.y; acc[1][2] += a.y*b.z; acc[1][3] += a.y*b.w;
            acc[2][0] += a.z*b.x; acc[2][1] += a.z*b.y; acc[2][2] += a.z*b.z; acc[2][3] += a.z*b.w;
            acc[3][0] += a.w*b.x; acc[3][1] += a.w*b.y; acc[3][2] += a.w*b.z; acc[3][3] += a.w*b.w;
        }
    }
#pragma unroll
    for (int i = 0; i < 4; i++) {
        int gm = row0 + (ty << 2) + i;
        if (gm >= SB) continue;
#pragma unroll
        for (int j = 0; j < 4; j++) {
            int gn = col0 + (tx << 2) + j;
            if (gn >= H3) continue;
            C[(long)gm * H3 + gn] = acc[i][j] + __ldg(&bias[gn]);
        }
    }
}

// ---------------- 128x128 split-bf16 tensor-core GEMM (R9 body) ----------------
__global__ void __launch_bounds__(256) k_mma128(
    const __nv_bfloat16* __restrict__ Ahi, const __nv_bfloat16* __restrict__ Alo,
    const __nv_bfloat16* __restrict__ Bhi, const __nv_bfloat16* __restrict__ Blo,
    const float* __restrict__ bias,
    float* __restrict__ C, long ldc,
    float* __restrict__ rowsum, int expmode,
    int M, int N, int K)
{
    __shared__ __nv_bfloat16 As[2][128][18];
    __shared__ __nv_bfloat16 Bs[2][128][18];
    int tid = threadIdx.x;
    int warp = tid >> 5, lane = tid & 31;
    int wm = warp >> 1, wn = warp & 1;
    int g = lane >> 2, tig = lane & 3;
    int m0 = blockIdx.y * 128, n0 = blockIdx.x * 128;

    float c[2][8][4];
#pragma unroll
    for (int mt = 0; mt < 2; mt++)
#pragma unroll
        for (int s = 0; s < 8; s++)
#pragma unroll
            for (int q = 0; q < 4; q++) c[mt][s][q] = 0.f;

    for (int kc = 0; kc < K; kc += 16) {
        __syncthreads();
#pragma unroll
        for (int it = 0; it < 4; it++) {
            int idx = it * 256 + tid;
            int row = idx >> 3, pr = idx & 7;
            {
                int gm = m0 + row;
                u32 vh = 0u, vl = 0u;
                if (gm < M) {
                    long gi = (long)gm * K + kc + pr * 2;
                    vh = *(const u32*)(Ahi + gi);
                    vl = *(const u32*)(Alo + gi);
                }
                *(u32*)&As[0][row][pr * 2] = vh;
                *(u32*)&As[1][row][pr * 2] = vl;
            }
            {
                int gn = n0 + row;
                u32 vh = 0u, vl = 0u;
                if (gn < N) {
                    long gi = (long)gn * K + kc + pr * 2;
                    vh = *(const u32*)(Bhi + gi);
                    vl = *(const u32*)(Blo + gi);
                }
                *(u32*)&Bs[0][row][pr * 2] = vh;
                *(u32*)&Bs[1][row][pr * 2] = vl;
            }
        }
        __syncthreads();

        u32 ah[2][4], al[2][4];
#pragma unroll
        for (int mt = 0; mt < 2; mt++) {
            int ar = wm * 32 + mt * 16 + g;
            ah[mt][0] = *(u32*)&As[0][ar][tig * 2];
            ah[mt][1] = *(u32*)&As[0][ar + 8][tig * 2];
            ah[mt][2] = *(u32*)&As[0][ar][tig * 2 + 8];
            ah[mt][3] = *(u32*)&As[0][ar + 8][tig * 2 + 8];
            al[mt][0] = *(u32*)&As[1][ar][tig * 2];
            al[mt][1] = *(u32*)&As[1][ar + 8][tig * 2];
            al[mt][2] = *(u32*)&As[1][ar][tig * 2 + 8];
            al[mt][3] = *(u32*)&As[1][ar + 8][tig * 2 + 8];
        }
#pragma unroll
        for (int sub = 0; sub < 8; sub++) {
            int bn = wn * 64 + sub * 8 + g;
            u32 bh[2], bl[2];
            bh[0] = *(u32*)&Bs[0][bn][tig * 2];
            bh[1] = *(u32*)&Bs[0][bn][tig * 2 + 8];
            bl[0] = *(u32*)&Bs[1][bn][tig * 2];
            bl[1] = *(u32*)&Bs[1][bn][tig * 2 + 8];
#pragma unroll
            for (int mt = 0; mt < 2; mt++) {
                mma_bf16(c[mt][sub], ah[mt], bh);
                mma_bf16(c[mt][sub], ah[mt], bl);
                mma_bf16(c[mt][sub], al[mt], bh);
            }
        }
    }

#pragma unroll
    for (int mt = 0; mt < 2; mt++) {
        int gmA = m0 + wm * 32 + mt * 16 + g;
        int gmB = gmA + 8;
        float sA = 0.f, sB = 0.f;
#pragma unroll
        for (int sub = 0; sub < 8; sub++) {
            int gn = n0 + wn * 64 + sub * 8 + tig * 2;
            if (gn < N) {
                float v0 = c[mt][sub][0], v1 = c[mt][sub][1];
                float v2 = c[mt][sub][2], v3 = c[mt][sub][3];
                if (bias) {
                    float b0 = __ldg(&bias[gn]), b1 = __ldg(&bias[gn + 1]);
                    v0 += b0; v1 += b1; v2 += b0; v3 += b1;
                }
                if (expmode) { v0 = fexp(v0); v1 = fexp(v1); v2 = fexp(v2); v3 = fexp(v3); }
                if (gmA < M) *(float2*)(C + (long)gmA * ldc + gn) = make_float2(v0, v1);
                if (gmB < M) *(float2*)(C + (long)gmB * ldc + gn) = make_float2(v2, v3);
                sA += v0 + v1; sB += v2 + v3;
            }
        }
        if (rowsum) {
            sA += __shfl_xor_sync(0xffffffffu, sA, 1);
            sA += __shfl_xor_sync(0xffffffffu, sA, 2);
            sB += __shfl_xor_sync(0xffffffffu, sB, 1);
            sB += __shfl_xor_sync(0xffffffffu, sB, 2);
            if (tig == 0) {
                if (gmA < M) atomicAdd(rowsum + gmA, sA);
                if (gmB < M) atomicAdd(rowsum + gmB, sB);
            }
        }
    }
}

// ---------------- persistent bi-GRU encoder (ffma2 inner loop) ----------------
__global__ void __launch_bounds__(384, 1) k_enc(
    const float* __restrict__ Whh_f, const float* __restrict__ Whh_b,
    const float* __restrict__ bhh_f, const float* __restrict__ bhh_b)
{
    __shared__ float hs[16 * 404];
    __shared__ float ghs[24 * 16];
    __shared__ float bsh[24];

    int dir = (int)(blockIdx.x / 50);
    int jb  = (int)(blockIdx.x % 50);
    int j0  = jb * 8;
    const float* Whh = dir ? Whh_b : Whh_f;
    const float* bhh = dir ? bhh_b : bhh_f;
    const float* GI  = d_S + (dir ? OGI1 : OGI0);
    float* OUT = d_S + (dir ? OHB : OHF);
    int tid = threadIdx.x;

    int kp = tid & 15;
    int rgi = (tid >> 4) & 3;
    int qg = tid >> 6;
    int kbase = kp * 25;

    if (tid < 24) { int gate = tid >> 3, jl = tid & 7; bsh[tid] = bhh[gate * 400 + j0 + jl]; }

    // W slice in registers, packed as 12 f32x2 pairs + 1 scalar per row
    ull  Wp[4][12];
    float Wlast[4];
#pragma unroll
    for (int i = 0; i < 4; i++) {
        int q = qg * 4 + i;
        int gate = q >> 3, jl = q & 7;
        const float* wr = Whh + (long)(gate * 400 + j0 + jl) * 400 + kbase;
#pragma unroll
        for (int kk = 0; kk < 12; kk++) Wp[i][kk] = pack2(wr[2 * kk], wr[2 * kk + 1]);
        Wlast[i] = wr[24];
    }
    __syncthreads();

    for (int t = 0; t < TENC; ++t) {
        int p = t & 1;
        const float4* Hin4 = (const float4*)d_Hbuf[dir][p];
        float* Hout = d_Hbuf[dir][p ^ 1];

        float ir = 0.f, iz = 0.f, ig = 0.f;
        int time = dir ? (TENC - 1 - t) : t;
        if (tid < 128) {
            int rr = tid & 15, jj = tid >> 4;
            long gib = ((long)time * Bb + rr) * H3 + j0 + jj;
            ir = GI[gib]; iz = GI[gib + 400]; ig = GI[gib + 800];
        }

        for (int i4 = tid; i4 < 1600; i4 += 384) {
            float4 v = __ldcg(Hin4 + i4);
            int row = i4 / 100, c4 = (i4 % 100) << 2;
            *(float4*)&hs[row * 404 + c4] = v;
        }
        __syncthreads();

        ull acc2[4][4];
        float accl[4][4];
#pragma unroll
        for (int i = 0; i < 4; i++)
#pragma unroll
            for (int j = 0; j < 4; j++) { acc2[i][j] = 0ULL; accl[i][j] = 0.f; }

        const float* h0 = hs + (rgi * 4 + 0) * 404 + kbase;
        const float* h1 = hs + (rgi * 4 + 1) * 404 + kbase;
        const float* h2 = hs + (rgi * 4 + 2) * 404 + kbase;
        const float* h3 = hs + (rgi * 4 + 3) * 404 + kbase;
#pragma unroll
        for (int kk = 0; kk < 12; kk++) {
            ull hp0 = pack2(h0[2 * kk], h0[2 * kk + 1]);
            ull hp1 = pack2(h1[2 * kk], h1[2 * kk + 1]);
            ull hp2 = pack2(h2[2 * kk], h2[2 * kk + 1]);
            ull hp3 = pack2(h3[2 * kk], h3[2 * kk + 1]);
#pragma unroll
            for (int i = 0; i < 4; i++) {
                ull w = Wp[i][kk];
                ffma2(acc2[i][0], w, hp0);
                ffma2(acc2[i][1], w, hp1);
                ffma2(acc2[i][2], w, hp2);
                ffma2(acc2[i][3], w, hp3);
            }
        }
        {
            float hv0 = h0[24], hv1 = h1[24], hv2 = h2[24], hv3 = h3[24];
#pragma unroll
            for (int i = 0; i < 4; i++) {
                accl[i][0] += Wlast[i] * hv0;
                accl[i][1] += Wlast[i] * hv1;
                accl[i][2] += Wlast[i] * hv2;
                accl[i][3] += Wlast[i] * hv3;
            }
        }

#pragma unroll
        for (int i = 0; i < 4; i++)
#pragma unroll
            for (int j = 0; j < 4; j++) {
                float lo, hi;
                unpack2(acc2[i][j], lo, hi);
                float v = lo + hi + accl[i][j];
                v += __shfl_xor_sync(0xffffffffu, v, 1);
                v += __shfl_xor_sync(0xffffffffu, v, 2);
                v += __shfl_xor_sync(0xffffffffu, v, 4);
                v += __shfl_xor_sync(0xffffffffu, v, 8);
                accl[i][j] = v;
            }
        if (kp == 0) {
#pragma unroll
            for (int i = 0; i < 4; i++) {
                float bb = bsh[qg * 4 + i];
#pragma unroll
                for (int j = 0; j < 4; j++)
                    ghs[(qg * 4 + i) * 16 + (rgi * 4 + j)] = accl[i][j] + bb;
            }
        }
        __syncthreads();

        if (tid < 128) {
            int rr = tid & 15, jj = tid >> 4;
            float hr_ = ghs[jj * 16 + rr];
            float hz_ = ghs[(8 + jj) * 16 + rr];
            float hg_ = ghs[(16 + jj) * 16 + rr];
            float hp  = hs[rr * 404 + j0 + jj];
            float rg_ = fsig(ir + hr_);
            float zg = fsig(iz + hz_);
            float gg = tanhf(ig + rg_ * hg_);
            float hn = (1.f - zg) * gg + zg * hp;
            Hout[rr * 400 + j0 + jj] = hn;
            OUT[((long)time * Bb + rr) * Hh + j0 + jj] = hn;
        }
        __syncthreads();
        if (tid == 0) {
            __threadfence();
            unsigned a = atomicAdd(&g_barcnt[dir], 1u);
            if (a == 50u * (unsigned)(t + 1) - 1u) {
                atomicAdd(&g_bargen[dir], 1u);
            } else {
                while (__ldcg((const unsigned*)&g_bargen[dir]) < (unsigned)(t + 1)) { __nanosleep(32); }
            }
            __threadfence();
        }
        __syncthreads();
    }
}

// ---------------- enc_out (B,T,H) and its transpose (B,H,T) ----------------
__global__ void k_encout() {
    long idx = (long)blockIdx.x * blockDim.x + threadIdx.x;
    if (idx >= (long)Bb * TENC * Hh) return;
    int b = (int)(idx / (TENC * Hh));
    int rem = (int)(idx % (TENC * Hh));
    int t = rem / Hh, h = rem % Hh;
    long src = ((long)t * Bb + b) * Hh + h;
    float v = d_S[OHF + src] + d_S[OHB + src];
    d_S[OEO + idx] = v;
    d_S[OEOT + (long)b * (Hh * TENC) + (long)h * TENC + t] = v;
}

// ---------------- decoder init ----------------
__global__ void k_dec_init(const float* __restrict__ slot) {
    int idx = blockIdx.x * blockDim.x + threadIdx.x;
    if (idx >= SB * Hh) return;
    int n = idx / Hh, h = idx % Hh;
    int s = n >> 4, b = n & 15;
    d_S[OH + idx]   = d_S[OHF + ((long)(TENC - 1) * Bb + b) * Hh + h]
                    + d_S[OHB + ((long)b) * Hh + h];
    d_S[ODIN + idx] = slot[s * Hh + h];
}

// ---------------- decoder GRU gates; zero rowsum + bf16 split of h ----------------
__global__ void k_dec_gates() {
    int idx = blockIdx.x * blockDim.x + threadIdx.x;
    if (idx < SB) d_S[ORSUM + idx] = 0.f;
    if (idx >= SB * Hh) return;
    int n = idx / Hh, j = idx % Hh;
    long gb = (long)n * H3 + j;
    float ir = d_S[OGI + gb], iz = d_S[OGI + gb + 400], ig = d_S[OGI + gb + 800];
    float hr = d_S[OGH + gb], hz = d_S[OGH + gb + 400], hg = d_S[OGH + gb + 800];
    float hp = d_S[OH + idx];
    float r = fsig(ir + hr);
    float z = fsig(iz + hz);
    float g = tanhf(ig + r * hg);
    float hn = (1.f - z) * g + z * hp;
    d_S[OH + idx] = hn;
    bsplit(hn, d_hhi[idx], d_hlo[idx]);
}

// ---------------- attention softmax over T=256 ----------------
__global__ void k_softmax_att() {
    int n = blockIdx.x, tid = threadIdx.x;
    __shared__ float red[256];
    float x = d_S[OPROB + (long)n * TENC + tid];
    red[tid] = x; __syncthreads();
    for (int o = 128; o; o >>= 1) { if (tid < o) red[tid] = fmaxf(red[tid], red[tid + o]); __syncthreads(); }
    float m = red[0]; __syncthreads();
    float e = fexp(x - m);
    red[tid] = e; __syncthreads();
    for (int o = 128; o; o >>= 1) { if (tid < o) red[tid] += red[tid + o]; __syncthreads(); }
    d_S[OPROB + (long)n * TENC + tid] = e / red[0];
}

// ---------------- sw (p_gen ratio) and (t==0) gate outputs ----------------
__global__ void k_sw_gate(const float* __restrict__ Wr, const float* __restrict__ br,
                          const float* __restrict__ Wg, const float* __restrict__ bg,
                          float* __restrict__ out, int t) {
    int warp = (blockIdx.x * blockDim.x + threadIdx.x) >> 5;
    int lane = threadIdx.x & 31;
    if (warp >= SB) return;
    int n = warp;
    float s = 0.f;
    for (int j = lane; j < H3; j += 32) {
        float v = (j < 400) ? d_S[OH + (long)n * Hh + j]
                : (j < 800) ? d_S[OCTX + (long)n * Hh + j - 400]
                            : d_S[ODIN + (long)n * Hh + j - 800];
        s += v * Wr[j];
    }
    for (int o = 16; o; o >>= 1) s += __shfl_xor_sync(0xffffffffu, s, o);
    if (lane == 0) d_S[OSW + n] = fsig(s + br[0]);
    if (t == 0) {
        for (int g = 0; g < Gg; g++) {
            float a = 0.f;
            for (int j = lane; j < Hh; j += 32) a += d_S[OCTX + (long)n * Hh + j] * Wg[g * Hh + j];
            for (int o = 16; o; o >>= 1) a += __shfl_xor_sync(0xffffffffu, a, o);
            if (lane == 0) out[PTR_OUT + (long)n * Gg + g] = a + bg[g];
        }
    }
}

// ---------------- fused finalize: scale out, scatter pointer, next din ----------------
// one block per row n (480 blocks x 256 threads)
__global__ void __launch_bounds__(256) k_finalize(
    float* __restrict__ out, const int* __restrict__ story,
    const int* __restrict__ tb, const float* __restrict__ emb, int t)
{
    int n = blockIdx.x, tid = threadIdx.x;
    int s = n >> 4, b = n & 15;
    float sc = d_S[OSW + n] / d_S[ORSUM + n];
    float* row = out + ((long)n * TDEC + t) * Vv;

    // scale exp(logits) -> sw * p_vocab   (4500 float4)
    for (int i = tid; i < Vv / 4; i += 256) {
        float4 e = *(const float4*)(row + i * 4);
        e.x *= sc; e.y *= sc; e.z *= sc; e.w *= sc;
        *(float4*)(row + i * 4) = e;
    }
    __syncthreads();

    // scatter pointer prob into this row (256 story positions, 1/thread)
    {
        int tok = story[b * TENC + tid];
        float v = (1.f - d_S[OSW + n]) * d_S[OPROB + (long)n * TENC + tid];
        atomicAdd(row + tok, v);
    }

    // next decoder input for this row
    {
        int tok = tb[(b * Ss + s) * TDEC + t];
        for (int h = tid; h < Hh; h += 256)
            d_S[ODIN + (long)n * Hh + h] = emb[(long)tok * Hh + h];
    }
}

// ---------------- host ----------------
extern "C" void kernel_launch(void* const* d_in, const int* in_sizes, int n_in,
                              void* d_out, int out_size) {
    const int*   story = (const int*)d_in[0];
    const int*   tb    = (const int*)d_in[1];
    const float* emb   = (const float*)d_in[2];
    const float* eWif  = (const float*)d_in[3];
    const float* eWhf  = (const float*)d_in[4];
    const float* ebif  = (const float*)d_in[5];
    const float* ebhf  = (const float*)d_in[6];
    const float* eWib  = (const float*)d_in[7];
    const float* eWhb  = (const float*)d_in[8];
    const float* ebib  = (const float*)d_in[9];
    const float* ebhb  = (const float*)d_in[10];
    const float* dWi   = (const float*)d_in[11];
    const float* dWh   = (const float*)d_in[12];
    const float* dbi   = (const float*)d_in[13];
    const float* dbh   = (const float*)d_in[14];
    const float* Wr    = (const float*)d_in[15];
    const float* br    = (const float*)d_in[16];
    const float* Wg    = (const float*)d_in[17];
    const float* bg    = (const float*)d_in[18];
    const float* slot  = (const float*)d_in[19];
    float* out = (float*)d_out;

    float* S = nullptr;
    cudaGetSymbolAddress((void**)&S, d_S);
    float* pGI0  = S + OGI0;
    float* pGI1  = S + OGI1;
    float* pEO   = S + OEO;
    float* pEOT  = S + OEOT;
    float* pH    = S + OH;
    float* pDIN  = S + ODIN;
    float* pGI   = S + OGI;
    float* pGH   = S + OGH;
    float* pPROB = S + OPROB;
    float* pCTX  = S + OCTX;
    float* pRS   = S + ORSUM;

    __nv_bfloat16 *xhi, *xlo, *wfhi, *wflo, *wbhi, *wblo, *ehi, *elo, *hhi, *hlo;
    cudaGetSymbolAddress((void**)&xhi, d_xhi);
    cudaGetSymbolAddress((void**)&xlo, d_xlo);
    cudaGetSymbolAddress((void**)&wfhi, d_wfhi);
    cudaGetSymbolAddress((void**)&wflo, d_wflo);
    cudaGetSymbolAddress((void**)&wbhi, d_wbhi);
    cudaGetSymbolAddress((void**)&wblo, d_wblo);
    cudaGetSymbolAddress((void**)&ehi, d_ehi);
    cudaGetSymbolAddress((void**)&elo, d_elo);
    cudaGetSymbolAddress((void**)&hhi, d_hhi);
    cudaGetSymbolAddress((void**)&hlo, d_hlo);

    k_init<<<32, 256>>>();
    k_embconv<<<(int)(((long)Vv * Hh + 255) / 256), 256>>>(emb);
    k_embed<<<(TENC * Bb * Hh + 255) / 256, 256>>>(story);
    k_wsplit<<<(H3 * Hh + 255) / 256, 256>>>(eWif, wfhi, wflo, H3 * Hh);
    k_wsplit<<<(H3 * Hh + 255) / 256, 256>>>(eWib, wbhi, wblo, H3 * Hh);

    // GI via tensor cores: (4096 x 1200 x 400)
    k_mma128<<<dim3(10, 32), 256>>>(xhi, xlo, wfhi, wflo, ebif, pGI0, H3, nullptr, 0, TENC * Bb, H3, Hh);
    k_mma128<<<dim3(10, 32), 256>>>(xhi, xlo, wbhi, wblo, ebib, pGI1, H3, nullptr, 0, TENC * Bb, H3, Hh);

    // persistent bidirectional GRU
    k_enc<<<100, 384>>>(eWhf, eWhb, ebhf, ebhb);

    k_encout<<<(Bb * TENC * Hh + 255) / 256, 256>>>();
    k_dec_init<<<(SB * Hh + 255) / 256, 256>>>(slot);

    for (int t = 0; t < TDEC; t++) {
        k_decgemm<<<dim3(19, 8, 2), 256>>>(pDIN, pH, dWi, dWh, dbi, dbh, pGI, pGH);
        k_dec_gates<<<(SB * Hh + 255) / 256, 256>>>();

        k_sgemm<<<dim3(4, 1, Bb), 256>>>(pH, Bb * Hh, Hh, pEO, Hh, (long)TENC * Hh,
                                         nullptr, pPROB, Bb * TENC, TENC, Ss, TENC, Hh);
        k_softmax_att<<<SB, 256>>>();
        k_sgemm<<<dim3(7, 1, Bb), 256>>>(pPROB, Bb * TENC, TENC, pEOT, TENC, (long)Hh * TENC,
                                         nullptr, pCTX, Bb * Hh, Hh, Ss, Hh, TENC);

        k_sw_gate<<<60, 256>>>(Wr, br, Wg, bg, out, t);

        // tensor-core logits: exp(logit) straight into out + rowsum
        k_mma128<<<dim3(141, 4), 256>>>(hhi, hlo, ehi, elo, nullptr,
                                        out + (long)t * Vv, (long)TDEC * Vv, pRS, 1, SB, Vv, Hh);

        // fused scale + scatter + next-din
        k_finalize<<<SB, 256>>>(out, story, tb, emb, t);
    }
}

// round 12
// speedup vs baseline: 1.0981x; 1.0263x over previous
#include <cuda_runtime.h>
#include <cuda_bf16.h>
#include <math.h>

#define Vv 18000
#define Hh 400
#define Bb 16
#define TENC 256
#define Ss 30
#define TDEC 8
#define Gg 3
#define SB 480
#define H3 1200
#define PTR_OUT 69120000L

typedef unsigned long long ull;
typedef unsigned int u32;

// ---------------- scratch ----------------
#define OGI0  1638400L
#define OGI1  6553600L
#define OHF   11468800L
#define OHB   13107200L
#define OEO   14745600L
#define OEOT  16384000L
#define OH    18022400L
#define ODIN  18214400L
#define OGI   18406400L
#define OGH   18982400L
#define OPROB 19558400L
#define OCTX  19681280L
#define OSW   19873280L
#define ORSUM 19873760L
#define STOT  19874720L

__device__ float d_S[STOT];
__device__ float d_Hbuf[2][2][Bb * Hh];
__device__ unsigned g_barcnt[2], g_bargen[2];
__device__ __nv_bfloat16 d_ehi[(long)Vv * Hh];
__device__ __nv_bfloat16 d_elo[(long)Vv * Hh];
__device__ __nv_bfloat16 d_hhi[SB * Hh];
__device__ __nv_bfloat16 d_hlo[SB * Hh];
__device__ __nv_bfloat16 d_xhi[TENC * Bb * Hh];
__device__ __nv_bfloat16 d_xlo[TENC * Bb * Hh];
__device__ __nv_bfloat16 d_wfhi[H3 * Hh], d_wflo[H3 * Hh];
__device__ __nv_bfloat16 d_wbhi[H3 * Hh], d_wblo[H3 * Hh];

// ---------------- packed f32x2 helpers ----------------
__device__ __forceinline__ ull pack2(float x, float y) {
    ull r; asm("mov.b64 %0, {%1, %2};" : "=l"(r) : "f"(x), "f"(y)); return r;
}
__device__ __forceinline__ void unpack2(ull v, float& x, float& y) {
    asm("mov.b64 {%0, %1}, %2;" : "=f"(x), "=f"(y) : "l"(v));
}
__device__ __forceinline__ void ffma2(ull& d, ull a, ull b) {
    asm("fma.rn.f32x2 %0, %1, %2, %3;" : "=l"(d) : "l"(a), "l"(b), "l"(d));
}

// ---------------- fast exp ----------------
__device__ __forceinline__ float fexp(float x) {
    x = fminf(fmaxf(x, -80.0f), 80.0f);
    float y = x * 1.4426950408889634f;
    int   i = __float2int_rn(y);
    float f = y - (float)i;
    float u = f * 0.6931471805599453f;
    float p = 1.0f + u * (1.0f + u * (0.5f + u * (0.16666667f +
              u * (0.041666668f + u * (0.008333334f + u * 0.0013888889f)))));
    return __int_as_float(__float_as_int(p) + (i << 23));
}
__device__ __forceinline__ float fsig(float x) { return 1.0f / (1.0f + fexp(-x)); }

__device__ __forceinline__ void bsplit(float v, __nv_bfloat16& hi, __nv_bfloat16& lo) {
    hi = __float2bfloat16(v);
    lo = __float2bfloat16(v - __bfloat162float(hi));
}

// ---------------- mma / ldmatrix ----------------
__device__ __forceinline__ void mma_bf16(float* c, const u32* a, const u32* b) {
    asm volatile(
        "mma.sync.aligned.m16n8k16.row.col.f32.bf16.bf16.f32 "
        "{%0,%1,%2,%3}, {%4,%5,%6,%7}, {%8,%9}, {%0,%1,%2,%3};"
        : "+f"(c[0]), "+f"(c[1]), "+f"(c[2]), "+f"(c[3])
        : "r"(a[0]), "r"(a[1]), "r"(a[2]), "r"(a[3]), "r"(b[0]), "r"(b[1]));
}
__device__ __forceinline__ void ldsm_x4(u32& r0, u32& r1, u32& r2, u32& r3, u32 addr) {
    asm volatile("ldmatrix.sync.aligned.m8n8.x4.shared.b16 {%0,%1,%2,%3}, [%4];"
        : "=r"(r0), "=r"(r1), "=r"(r2), "=r"(r3) : "r"(addr));
}

// ---------------- init ----------------
__global__ void k_init() {
    int tid = blockIdx.x * blockDim.x + threadIdx.x;
    if (tid == 0) {
        g_barcnt[0] = 0u; g_barcnt[1] = 0u;
        g_bargen[0] = 0u; g_bargen[1] = 0u;
    }
    for (int i = tid; i < 2 * 2 * Bb * Hh; i += gridDim.x * blockDim.x)
        ((float*)d_Hbuf)[i] = 0.0f;
}

// ---------------- one-time conversions ----------------
__global__ void k_embconv(const float* __restrict__ emb) {
    long idx = (long)blockIdx.x * blockDim.x + threadIdx.x;
    if (idx >= (long)Vv * Hh) return;
    bsplit(emb[idx], d_ehi[idx], d_elo[idx]);
}
__global__ void k_wsplit(const float* __restrict__ w, __nv_bfloat16* hi, __nv_bfloat16* lo, int n) {
    int idx = blockIdx.x * blockDim.x + threadIdx.x;
    if (idx >= n) return;
    bsplit(w[idx], hi[idx], lo[idx]);
}
__global__ void k_embed(const int* __restrict__ story) {
    long idx = (long)blockIdx.x * blockDim.x + threadIdx.x;
    if (idx >= (long)TENC * Bb * Hh) return;
    int h = (int)(idx % Hh);
    int tb = (int)(idx / Hh);
    int b = tb & 15, t = tb >> 4;
    long src = (long)story[b * TENC + t] * Hh + h;
    d_xhi[idx] = d_ehi[src];
    d_xlo[idx] = d_elo[src];
}

// ---------------- generic batched TN SGEMM (64x64x16) ----------------
__global__ void __launch_bounds__(256) k_sgemm(
    const float* __restrict__ A, int lda, long sA,
    const float* __restrict__ Bw, int ldb, long sB,
    const float* __restrict__ bias,
    float* __restrict__ C, int ldc, long sC,
    int M, int N, int K)
{
    A  += (long)blockIdx.z * sA;
    Bw += (long)blockIdx.z * sB;
    C  += (long)blockIdx.z * sC;
    __shared__ float As[16][68];
    __shared__ float Bs[16][68];
    int tid = threadIdx.x;
    int tx = tid & 15, ty = tid >> 4;
    int row0 = blockIdx.y * 64, col0 = blockIdx.x * 64;
    int lm = tid >> 2, lk = (tid & 3) << 2;
    float acc[4][4] = {{0.f}};

    for (int k0 = 0; k0 < K; k0 += 16) {
        float4 va = make_float4(0.f, 0.f, 0.f, 0.f);
        float4 vb = make_float4(0.f, 0.f, 0.f, 0.f);
        if (row0 + lm < M) va = *(const float4*)(A + (long)(row0 + lm) * lda + k0 + lk);
        if (col0 + lm < N) vb = *(const float4*)(Bw + (long)(col0 + lm) * ldb + k0 + lk);
        __syncthreads();
        As[lk][lm] = va.x; As[lk+1][lm] = va.y; As[lk+2][lm] = va.z; As[lk+3][lm] = va.w;
        Bs[lk][lm] = vb.x; Bs[lk+1][lm] = vb.y; Bs[lk+2][lm] = vb.z; Bs[lk+3][lm] = vb.w;
        __syncthreads();
#pragma unroll
        for (int kk = 0; kk < 16; kk++) {
            float4 a = *(const float4*)&As[kk][ty << 2];
            float4 b = *(const float4*)&Bs[kk][tx << 2];
            acc[0][0] += a.x*b.x; acc[0][1] += a.x*b.y; acc[0][2] += a.x*b.z; acc[0][3] += a.x*b.w;
            acc[1][0] += a.y*b.x; acc[1][1] += a.y*b.y; acc[1][2] += a.y*b.z; acc[1][3] += a.y*b.w;
            acc[2][0] += a.z*b.x; acc[2][1] += a.z*b.y; acc[2][2] += a.z*b.z; acc[2][3] += a.z*b.w;
            acc[3][0] += a.w*b.x; acc[3][1] += a.w*b.y; acc[3][2] += a.w*b.z; acc[3][3] += a.w*b.w;
        }
    }
#pragma unroll
    for (int i = 0; i < 4; i++) {
        int gm = row0 + (ty << 2) + i;
        if (gm >= M) continue;
#pragma unroll
        for (int j = 0; j < 4; j++) {
            int gn = col0 + (tx << 2) + j;
            if (gn >= N) continue;
            float v = acc[i][j];
            if (bias) v += __ldg(&bias[gn]);
            C[(long)gm * ldc + gn] = v;
        }
    }
}

// ---------------- fused decoder GRU GEMMs ----------------
__global__ void __launch_bounds__(256) k_decgemm(
    const float* __restrict__ A0, const float* __restrict__ A1,
    const float* __restrict__ B0, const float* __restrict__ B1,
    const float* __restrict__ bias0, const float* __restrict__ bias1,
    float* __restrict__ C0, float* __restrict__ C1)
{
    const float* A = blockIdx.z ? A1 : A0;
    const float* Bw = blockIdx.z ? B1 : B0;
    const float* bias = blockIdx.z ? bias1 : bias0;
    float* C = blockIdx.z ? C1 : C0;
    __shared__ float As[16][68];
    __shared__ float Bs[16][68];
    int tid = threadIdx.x;
    int tx = tid & 15, ty = tid >> 4;
    int row0 = blockIdx.y * 64, col0 = blockIdx.x * 64;
    int lm = tid >> 2, lk = (tid & 3) << 2;
    float acc[4][4] = {{0.f}};

    for (int k0 = 0; k0 < Hh; k0 += 16) {
        float4 va = make_float4(0.f, 0.f, 0.f, 0.f);
        float4 vb = make_float4(0.f, 0.f, 0.f, 0.f);
        if (row0 + lm < SB) va = *(const float4*)(A + (long)(row0 + lm) * Hh + k0 + lk);
        if (col0 + lm < H3) vb = *(const float4*)(Bw + (long)(col0 + lm) * Hh + k0 + lk);
        __syncthreads();
        As[lk][lm] = va.x; As[lk+1][lm] = va.y; As[lk+2][lm] = va.z; As[lk+3][lm] = va.w;
        Bs[lk][lm] = vb.x; Bs[lk+1][lm] = vb.y; Bs[lk+2][lm] = vb.z; Bs[lk+3][lm] = vb.w;
        __syncthreads();
#pragma unroll
        for (int kk = 0; kk < 16; kk++) {
            float4 a = *(const float4*)&As[kk][ty << 2];
            float4 b = *(const float4*)&Bs[kk][tx << 2];
            acc[0][0] += a.x*b.x; acc[0][1] += a.x*b.y; acc[0][2] += a.x*b.z; acc[0][3] += a.x*b.w;
            acc[1][0] += a.y*b.x; acc[1][1] += a.y*b.y; acc[1][2] += a.y*b.z; acc[1][3] += a.y*b.w;
            acc[2][0] += a.z*b.x; acc[2][1] += a.z*b.y; acc[2][2] += a.z*b.z; acc[2][3] += a.z*b.w;
            acc[3][0] += a.w*b.x; acc[3][1] += a.w*b.y; acc[3][2] += a.w*b.z; acc[3][3] += a.w*b.w;
        }
    }
#pragma unroll
    for (int i = 0; i < 4; i++) {
        int gm = row0 + (ty << 2) + i;
        if (gm >= SB) continue;
#pragma unroll
        for (int j = 0; j < 4; j++) {
            int gn = col0 + (tx << 2) + j;
            if (gn >= H3) continue;
            C[(long)gm * H3 + gn] = acc[i][j] + __ldg(&bias[gn]);
        }
    }
}

// ---------------- 128x128 split-bf16 tensor-core GEMM (ldmatrix fragments) ----------------
// smem rows padded to 24 halfwords (48B): 16B-aligned rows + conflict-free LDSM.
__global__ void __launch_bounds__(256) k_mma128(
    const __nv_bfloat16* __restrict__ Ahi, const __nv_bfloat16* __restrict__ Alo,
    const __nv_bfloat16* __restrict__ Bhi, const __nv_bfloat16* __restrict__ Blo,
    const float* __restrict__ bias,
    float* __restrict__ C, long ldc,
    float* __restrict__ rowsum, int expmode,
    int M, int N, int K)
{
    __shared__ __nv_bfloat16 As[2][128][24];
    __shared__ __nv_bfloat16 Bs[2][128][24];
    int tid = threadIdx.x;
    int warp = tid >> 5, lane = tid & 31;
    int wm = warp >> 1, wn = warp & 1;
    int g = lane >> 2, tig = lane & 3;
    int m0 = blockIdx.y * 128, n0 = blockIdx.x * 128;

    // ldmatrix lane address offsets (in halfwords, within a [128][24] plane)
    // A tile (16x16 at row base R): row = R + (lane&15), col = (lane>>4)*8
    // B pair (16 n-rows x 16 k at row base R): row = R + (lane&7) + ((lane>>4)<<3), col = ((lane>>3)&1)*8
    u32 aA0 = (u32)__cvta_generic_to_shared(&As[0][0][0]);
    u32 aA1 = (u32)__cvta_generic_to_shared(&As[1][0][0]);
    u32 aB0 = (u32)__cvta_generic_to_shared(&Bs[0][0][0]);
    u32 aB1 = (u32)__cvta_generic_to_shared(&Bs[1][0][0]);
    int arowA = (lane & 15);
    int acolA = (lane >> 4) * 8;
    int arowB = (lane & 7) + ((lane >> 4) << 3);
    int acolB = ((lane >> 3) & 1) * 8;
    u32 offA[2], offB[4];
#pragma unroll
    for (int mt = 0; mt < 2; mt++)
        offA[mt] = (u32)(((wm * 32 + mt * 16 + arowA) * 24 + acolA) * 2);
#pragma unroll
    for (int sp = 0; sp < 4; sp++)
        offB[sp] = (u32)(((wn * 64 + sp * 16 + arowB) * 24 + acolB) * 2);

    float c[2][8][4];
#pragma unroll
    for (int mt = 0; mt < 2; mt++)
#pragma unroll
        for (int s = 0; s < 8; s++)
#pragma unroll
            for (int q = 0; q < 4; q++) c[mt][s][q] = 0.f;

    for (int kc = 0; kc < K; kc += 16) {
        __syncthreads();
#pragma unroll
        for (int it = 0; it < 4; it++) {
            int idx = it * 256 + tid;
            int row = idx >> 3, pr = idx & 7;
            {
                int gm = m0 + row;
                u32 vh = 0u, vl = 0u;
                if (gm < M) {
                    long gi = (long)gm * K + kc + pr * 2;
                    vh = *(const u32*)(Ahi + gi);
                    vl = *(const u32*)(Alo + gi);
                }
                *(u32*)&As[0][row][pr * 2] = vh;
                *(u32*)&As[1][row][pr * 2] = vl;
            }
            {
                int gn = n0 + row;
                u32 vh = 0u, vl = 0u;
                if (gn < N) {
                    long gi = (long)gn * K + kc + pr * 2;
                    vh = *(const u32*)(Bhi + gi);
                    vl = *(const u32*)(Blo + gi);
                }
                *(u32*)&Bs[0][row][pr * 2] = vh;
                *(u32*)&Bs[1][row][pr * 2] = vl;
            }
        }
        __syncthreads();

        u32 ah[2][4], al[2][4];
#pragma unroll
        for (int mt = 0; mt < 2; mt++) {
            ldsm_x4(ah[mt][0], ah[mt][1], ah[mt][2], ah[mt][3], aA0 + offA[mt]);
            ldsm_x4(al[mt][0], al[mt][1], al[mt][2], al[mt][3], aA1 + offA[mt]);
        }
#pragma unroll
        for (int sp = 0; sp < 4; sp++) {
            u32 bh[4], bl[4];   // {b0_even, b1_even, b0_odd, b1_odd}
            ldsm_x4(bh[0], bh[1], bh[2], bh[3], aB0 + offB[sp]);
            ldsm_x4(bl[0], bl[1], bl[2], bl[3], aB1 + offB[sp]);
#pragma unroll
            for (int half = 0; half < 2; half++) {
                int sub = sp * 2 + half;
#pragma unroll
                for (int mt = 0; mt < 2; mt++) {
                    mma_bf16(c[mt][sub], ah[mt], bh + half * 2);
                    mma_bf16(c[mt][sub], ah[mt], bl + half * 2);
                    mma_bf16(c[mt][sub], al[mt], bh + half * 2);
                }
            }
        }
    }

#pragma unroll
    for (int mt = 0; mt < 2; mt++) {
        int gmA = m0 + wm * 32 + mt * 16 + g;
        int gmB = gmA + 8;
        float sA = 0.f, sB = 0.f;
#pragma unroll
        for (int sub = 0; sub < 8; sub++) {
            int gn = n0 + wn * 64 + sub * 8 + tig * 2;
            if (gn < N) {
                float v0 = c[mt][sub][0], v1 = c[mt][sub][1];
                float v2 = c[mt][sub][2], v3 = c[mt][sub][3];
                if (bias) {
                    float b0 = __ldg(&bias[gn]), b1 = __ldg(&bias[gn + 1]);
                    v0 += b0; v1 += b1; v2 += b0; v3 += b1;
                }
                if (expmode) { v0 = fexp(v0); v1 = fexp(v1); v2 = fexp(v2); v3 = fexp(v3); }
                if (gmA < M) *(float2*)(C + (long)gmA * ldc + gn) = make_float2(v0, v1);
                if (gmB < M) *(float2*)(C + (long)gmB * ldc + gn) = make_float2(v2, v3);
                sA += v0 + v1; sB += v2 + v3;
            }
        }
        if (rowsum) {
            sA += __shfl_xor_sync(0xffffffffu, sA, 1);
            sA += __shfl_xor_sync(0xffffffffu, sA, 2);
            sB += __shfl_xor_sync(0xffffffffu, sB, 1);
            sB += __shfl_xor_sync(0xffffffffu, sB, 2);
            if (tig == 0) {
                if (gmA < M) atomicAdd(rowsum + gmA, sA);
                if (gmB < M) atomicAdd(rowsum + gmB, sB);
            }
        }
    }
}

// ---------------- persistent bi-GRU encoder (ffma2 + acq/rel barrier) ----------------
__global__ void __launch_bounds__(384, 1) k_enc(
    const float* __restrict__ Whh_f, const float* __restrict__ Whh_b,
    const float* __restrict__ bhh_f, const float* __restrict__ bhh_b)
{
    __shared__ float hs[16 * 404];
    __shared__ float ghs[24 * 16];
    __shared__ float bsh[24];

    int dir = (int)(blockIdx.x / 50);
    int jb  = (int)(blockIdx.x % 50);
    int j0  = jb * 8;
    const float* Whh = dir ? Whh_b : Whh_f;
    const float* bhh = dir ? bhh_b : bhh_f;
    const float* GI  = d_S + (dir ? OGI1 : OGI0);
    float* OUT = d_S + (dir ? OHB : OHF);
    unsigned* cntp = &g_barcnt[dir];
    unsigned* genp = &g_bargen[dir];
    int tid = threadIdx.x;

    int kp = tid & 15;
    int rgi = (tid >> 4) & 3;
    int qg = tid >> 6;
    int kbase = kp * 25;

    if (tid < 24) { int gate = tid >> 3, jl = tid & 7; bsh[tid] = bhh[gate * 400 + j0 + jl]; }

    ull  Wp[4][12];
    float Wlast[4];
#pragma unroll
    for (int i = 0; i < 4; i++) {
        int q = qg * 4 + i;
        int gate = q >> 3, jl = q & 7;
        const float* wr = Whh + (long)(gate * 400 + j0 + jl) * 400 + kbase;
#pragma unroll
        for (int kk = 0; kk < 12; kk++) Wp[i][kk] = pack2(wr[2 * kk], wr[2 * kk + 1]);
        Wlast[i] = wr[24];
    }
    __syncthreads();

    for (int t = 0; t < TENC; ++t) {
        int p = t & 1;
        const float4* Hin4 = (const float4*)d_Hbuf[dir][p];
        float* Hout = d_Hbuf[dir][p ^ 1];

        float ir = 0.f, iz = 0.f, ig = 0.f;
        int time = dir ? (TENC - 1 - t) : t;
        if (tid < 128) {
            int rr = tid & 15, jj = tid >> 4;
            long gib = ((long)time * Bb + rr) * H3 + j0 + jj;
            ir = GI[gib]; iz = GI[gib + 400]; ig = GI[gib + 800];
        }

        for (int i4 = tid; i4 < 1600; i4 += 384) {
            float4 v = __ldcg(Hin4 + i4);
            int row = i4 / 100, c4 = (i4 % 100) << 2;
            *(float4*)&hs[row * 404 + c4] = v;
        }
        __syncthreads();

        ull acc2[4][4];
        float accl[4][4];
#pragma unroll
        for (int i = 0; i < 4; i++)
#pragma unroll
            for (int j = 0; j < 4; j++) { acc2[i][j] = 0ULL; accl[i][j] = 0.f; }

        const float* h0 = hs + (rgi * 4 + 0) * 404 + kbase;
        const float* h1 = hs + (rgi * 4 + 1) * 404 + kbase;
        const float* h2 = hs + (rgi * 4 + 2) * 404 + kbase;
        const float* h3 = hs + (rgi * 4 + 3) * 404 + kbase;
#pragma unroll
        for (int kk = 0; kk < 12; kk++) {
            ull hp0 = pack2(h0[2 * kk], h0[2 * kk + 1]);
            ull hp1 = pack2(h1[2 * kk], h1[2 * kk + 1]);
            ull hp2 = pack2(h2[2 * kk], h2[2 * kk + 1]);
            ull hp3 = pack2(h3[2 * kk], h3[2 * kk + 1]);
#pragma unroll
            for (int i = 0; i < 4; i++) {
                ull w = Wp[i][kk];
                ffma2(acc2[i][0], w, hp0);
                ffma2(acc2[i][1], w, hp1);
                ffma2(acc2[i][2], w, hp2);
                ffma2(acc2[i][3], w, hp3);
            }
        }
        {
            float hv0 = h0[24], hv1 = h1[24], hv2 = h2[24], hv3 = h3[24];
#pragma unroll
            for (int i = 0; i < 4; i++) {
                accl[i][0] += Wlast[i] * hv0;
                accl[i][1] += Wlast[i] * hv1;
                accl[i][2] += Wlast[i] * hv2;
                accl[i][3] += Wlast[i] * hv3;
            }
        }

#pragma unroll
        for (int i = 0; i < 4; i++)
#pragma unroll
            for (int j = 0; j < 4; j++) {
                float lo, hi;
                unpack2(acc2[i][j], lo, hi);
                float v = lo + hi + accl[i][j];
                v += __shfl_xor_sync(0xffffffffu, v, 1);
                v += __shfl_xor_sync(0xffffffffu, v, 2);
                v += __shfl_xor_sync(0xffffffffu, v, 4);
                v += __shfl_xor_sync(0xffffffffu, v, 8);
                accl[i][j] = v;
            }
        if (kp == 0) {
#pragma unroll
            for (int i = 0; i < 4; i++) {
                float bb = bsh[qg * 4 + i];
#pragma unroll
                for (int j = 0; j < 4; j++)
                    ghs[(qg * 4 + i) * 16 + (rgi * 4 + j)] = accl[i][j] + bb;
            }
        }
        __syncthreads();

        float hn = 0.f;
        int rr = tid & 15, jj = tid >> 4;
        if (tid < 128) {
            float hr_ = ghs[jj * 16 + rr];
            float hz_ = ghs[(8 + jj) * 16 + rr];
            float hg_ = ghs[(16 + jj) * 16 + rr];
            float hp  = hs[rr * 404 + j0 + jj];
            float rg_ = fsig(ir + hr_);
            float zg = fsig(iz + hz_);
            float gg = tanhf(ig + rg_ * hg_);
            hn = (1.f - zg) * gg + zg * hp;
            Hout[rr * 400 + j0 + jj] = hn;       // cross-block state: store first
        }
        __syncthreads();                          // all Hout stores ordered before arrival
        if (tid == 0) {
            unsigned a;
            asm volatile("atom.acq_rel.gpu.add.u32 %0, [%1], 1;"
                         : "=r"(a) : "l"(cntp) : "memory");
            if (a == 50u * (unsigned)(t + 1) - 1u) {
                asm volatile("red.release.gpu.add.u32 [%0], 1;" :: "l"(genp) : "memory");
            } else {
                unsigned gv;
                while (1) {
                    asm volatile("ld.acquire.gpu.u32 %0, [%1];" : "=r"(gv) : "l"(genp) : "memory");
                    if (gv >= (unsigned)(t + 1)) break;
                    __nanosleep(16);
                }
            }
        }
        // OUT store (consumed only after kernel ends) off the critical path
        if (tid < 128)
            OUT[((long)time * Bb + rr) * Hh + j0 + jj] = hn;
        __syncthreads();
    }
}

// ---------------- enc_out (B,T,H) and its transpose (B,H,T) ----------------
__global__ void k_encout() {
    long idx = (long)blockIdx.x * blockDim.x + threadIdx.x;
    if (idx >= (long)Bb * TENC * Hh) return;
    int b = (int)(idx / (TENC * Hh));
    int rem = (int)(idx % (TENC * Hh));
    int t = rem / Hh, h = rem % Hh;
    long src = ((long)t * Bb + b) * Hh + h;
    float v = d_S[OHF + src] + d_S[OHB + src];
    d_S[OEO + idx] = v;
    d_S[OEOT + (long)b * (Hh * TENC) + (long)h * TENC + t] = v;
}

// ---------------- decoder init ----------------
__global__ void k_dec_init(const float* __restrict__ slot) {
    int idx = blockIdx.x * blockDim.x + threadIdx.x;
    if (idx >= SB * Hh) return;
    int n = idx / Hh, h = idx % Hh;
    int s = n >> 4, b = n & 15;
    d_S[OH + idx]   = d_S[OHF + ((long)(TENC - 1) * Bb + b) * Hh + h]
                    + d_S[OHB + ((long)b) * Hh + h];
    d_S[ODIN + idx] = slot[s * Hh + h];
}

// ---------------- decoder GRU gates; zero rowsum + bf16 split of h ----------------
__global__ void k_dec_gates() {
    int idx = blockIdx.x * blockDim.x + threadIdx.x;
    if (idx < SB) d_S[ORSUM + idx] = 0.f;
    if (idx >= SB * Hh) return;
    int n = idx / Hh, j = idx % Hh;
    long gb = (long)n * H3 + j;
    float ir = d_S[OGI + gb], iz = d_S[OGI + gb + 400], ig = d_S[OGI + gb + 800];
    float hr = d_S[OGH + gb], hz = d_S[OGH + gb + 400], hg = d_S[OGH + gb + 800];
    float hp = d_S[OH + idx];
    float r = fsig(ir + hr);
    float z = fsig(iz + hz);
    float g = tanhf(ig + r * hg);
    float hn = (1.f - z) * g + z * hp;
    d_S[OH + idx] = hn;
    bsplit(hn, d_hhi[idx], d_hlo[idx]);
}

// ---------------- attention softmax over T=256 ----------------
__global__ void k_softmax_att() {
    int n = blockIdx.x, tid = threadIdx.x;
    __shared__ float red[256];
    float x = d_S[OPROB + (long)n * TENC + tid];
    red[tid] = x; __syncthreads();
    for (int o = 128; o; o >>= 1) { if (tid < o) red[tid] = fmaxf(red[tid], red[tid + o]); __syncthreads(); }
    float m = red[0]; __syncthreads();
    float e = fexp(x - m);
    red[tid] = e; __syncthreads();
    for (int o = 128; o; o >>= 1) { if (tid < o) red[tid] += red[tid + o]; __syncthreads(); }
    d_S[OPROB + (long)n * TENC + tid] = e / red[0];
}

// ---------------- sw (p_gen ratio) and (t==0) gate outputs ----------------
__global__ void k_sw_gate(const float* __restrict__ Wr, const float* __restrict__ br,
                          const float* __restrict__ Wg, const float* __restrict__ bg,
                          float* __restrict__ out, int t) {
    int warp = (blockIdx.x * blockDim.x + threadIdx.x) >> 5;
    int lane = threadIdx.x & 31;
    if (warp >= SB) return;
    int n = warp;
    float s = 0.f;
    for (int j = lane; j < H3; j += 32) {
        float v = (j < 400) ? d_S[OH + (long)n * Hh + j]
                : (j < 800) ? d_S[OCTX + (long)n * Hh + j - 400]
                            : d_S[ODIN + (long)n * Hh + j - 800];
        s += v * Wr[j];
    }
    for (int o = 16; o; o >>= 1) s += __shfl_xor_sync(0xffffffffu, s, o);
    if (lane == 0) d_S[OSW + n] = fsig(s + br[0]);
    if (t == 0) {
        for (int g = 0; g < Gg; g++) {
            float a = 0.f;
            for (int j = lane; j < Hh; j += 32) a += d_S[OCTX + (long)n * Hh + j] * Wg[g * Hh + j];
            for (int o = 16; o; o >>= 1) a += __shfl_xor_sync(0xffffffffu, a, o);
            if (lane == 0) out[PTR_OUT + (long)n * Gg + g] = a + bg[g];
        }
    }
}

// ---------------- fused finalize: scale out, scatter pointer, next din ----------------
__global__ void __launch_bounds__(256) k_finalize(
    float* __restrict__ out, const int* __restrict__ story,
    const int* __restrict__ tb, const float* __restrict__ emb, int t)
{
    int n = blockIdx.x, tid = threadIdx.x;
    int s = n >> 4, b = n & 15;
    float sc = d_S[OSW + n] / d_S[ORSUM + n];
    float* row = out + ((long)n * TDEC + t) * Vv;

    for (int i = tid; i < Vv / 4; i += 256) {
        float4 e = *(const float4*)(row + i * 4);
        e.x *= sc; e.y *= sc; e.z *= sc; e.w *= sc;
        *(float4*)(row + i * 4) = e;
    }
    __syncthreads();

    {
        int tok = story[b * TENC + tid];
        float v = (1.f - d_S[OSW + n]) * d_S[OPROB + (long)n * TENC + tid];
        atomicAdd(row + tok, v);
    }
    {
        int tok = tb[(b * Ss + s) * TDEC + t];
        for (int h = tid; h < Hh; h += 256)
            d_S[ODIN + (long)n * Hh + h] = emb[(long)tok * Hh + h];
    }
}

// ---------------- host ----------------
extern "C" void kernel_launch(void* const* d_in, const int* in_sizes, int n_in,
                              void* d_out, int out_size) {
    const int*   story = (const int*)d_in[0];
    const int*   tb    = (const int*)d_in[1];
    const float* emb   = (const float*)d_in[2];
    const float* eWif  = (const float*)d_in[3];
    const float* eWhf  = (const float*)d_in[4];
    const float* ebif  = (const float*)d_in[5];
    const float* ebhf  = (const float*)d_in[6];
    const float* eWib  = (const float*)d_in[7];
    const float* eWhb  = (const float*)d_in[8];
    const float* ebib  = (const float*)d_in[9];
    const float* ebhb  = (const float*)d_in[10];
    const float* dWi   = (const float*)d_in[11];
    const float* dWh   = (const float*)d_in[12];
    const float* dbi   = (const float*)d_in[13];
    const float* dbh   = (const float*)d_in[14];
    const float* Wr    = (const float*)d_in[15];
    const float* br    = (const float*)d_in[16];
    const float* Wg    = (const float*)d_in[17];
    const float* bg    = (const float*)d_in[18];
    const float* slot  = (const float*)d_in[19];
    float* out = (float*)d_out;

    float* S = nullptr;
    cudaGetSymbolAddress((void**)&S, d_S);
    float* pGI0  = S + OGI0;
    float* pGI1  = S + OGI1;
    float* pEO   = S + OEO;
    float* pEOT  = S + OEOT;
    float* pH    = S + OH;
    float* pDIN  = S + ODIN;
    float* pGI   = S + OGI;
    float* pGH   = S + OGH;
    float* pPROB = S + OPROB;
    float* pCTX  = S + OCTX;
    float* pRS   = S + ORSUM;

    __nv_bfloat16 *xhi, *xlo, *wfhi, *wflo, *wbhi, *wblo, *ehi, *elo, *hhi, *hlo;
    cudaGetSymbolAddress((void**)&xhi, d_xhi);
    cudaGetSymbolAddress((void**)&xlo, d_xlo);
    cudaGetSymbolAddress((void**)&wfhi, d_wfhi);
    cudaGetSymbolAddress((void**)&wflo, d_wflo);
    cudaGetSymbolAddress((void**)&wbhi, d_wbhi);
    cudaGetSymbolAddress((void**)&wblo, d_wblo);
    cudaGetSymbolAddress((void**)&ehi, d_ehi);
    cudaGetSymbolAddress((void**)&elo, d_elo);
    cudaGetSymbolAddress((void**)&hhi, d_hhi);
    cudaGetSymbolAddress((void**)&hlo, d_hlo);

    k_init<<<32, 256>>>();
    k_embconv<<<(int)(((long)Vv * Hh + 255) / 256), 256>>>(emb);
    k_embed<<<(TENC * Bb * Hh + 255) / 256, 256>>>(story);
    k_wsplit<<<(H3 * Hh + 255) / 256, 256>>>(eWif, wfhi, wflo, H3 * Hh);
    k_wsplit<<<(H3 * Hh + 255) / 256, 256>>>(eWib, wbhi, wblo, H3 * Hh);

    // GI via tensor cores: (4096 x 1200 x 400)
    k_mma128<<<dim3(10, 32), 256>>>(xhi, xlo, wfhi, wflo, ebif, pGI0, H3, nullptr, 0, TENC * Bb, H3, Hh);
    k_mma128<<<dim3(10, 32), 256>>>(xhi, xlo, wbhi, wblo, ebib, pGI1, H3, nullptr, 0, TENC * Bb, H3, Hh);

    // persistent bidirectional GRU
    k_enc<<<100, 384>>>(eWhf, eWhb, ebhf, ebhb);

    k_encout<<<(Bb * TENC * Hh + 255) / 256, 256>>>();
    k_dec_init<<<(SB * Hh + 255) / 256, 256>>>(slot);

    for (int t = 0; t < TDEC; t++) {
        k_decgemm<<<dim3(19, 8, 2), 256>>>(pDIN, pH, dWi, dWh, dbi, dbh, pGI, pGH);
        k_dec_gates<<<(SB * Hh + 255) / 256, 256>>>();

        k_sgemm<<<dim3(4, 1, Bb), 256>>>(pH, Bb * Hh, Hh, pEO, Hh, (long)TENC * Hh,
                                         nullptr, pPROB, Bb * TENC, TENC, Ss, TENC, Hh);
        k_softmax_att<<<SB, 256>>>();
        k_sgemm<<<dim3(7, 1, Bb), 256>>>(pPROB, Bb * TENC, TENC, pEOT, TENC, (long)Hh * TENC,
                                         nullptr, pCTX, Bb * Hh, Hh, Ss, Hh, TENC);

        k_sw_gate<<<60, 256>>>(Wr, br, Wg, bg, out, t);

        // tensor-core logits (ldmatrix): exp(logit) straight into out + rowsum
        k_mma128<<<dim3(141, 4), 256>>>(hhi, hlo, ehi, elo, nullptr,
                                        out + (long)t * Vv, (long)TDEC * Vv, pRS, 1, SB, Vv, Hh);

        k_finalize<<<SB, 256>>>(out, story, tb, emb, t);
    }
}

// round 13
// speedup vs baseline: 1.1151x; 1.0155x over previous
#include <cuda_runtime.h>
#include <cuda_bf16.h>
#include <math.h>

#define Vv 18000
#define Hh 400
#define Bb 16
#define TENC 256
#define Ss 30
#define TDEC 8
#define Gg 3
#define SB 480
#define H3 1200
#define PTR_OUT 69120000L

typedef unsigned long long ull;
typedef unsigned int u32;

// ---------------- scratch ----------------
#define OGI0  1638400L
#define OGI1  6553600L
#define OHF   11468800L
#define OHB   13107200L
#define OEO   14745600L
#define OEOT  16384000L
#define OH    18022400L
#define ODIN  18214400L
#define OGI   18406400L
#define OGH   18982400L
#define OPROB 19558400L
#define OCTX  19681280L
#define OSW   19873280L
#define ORSUM 19873760L
#define STOT  19874720L

__device__ float d_S[STOT];
__device__ float d_Hbuf[2][2][Bb * Hh];
__device__ unsigned g_barcnt[2], g_bargen[2];
__device__ __nv_bfloat16 d_ehi[(long)Vv * Hh];
__device__ __nv_bfloat16 d_elo[(long)Vv * Hh];
__device__ __nv_bfloat16 d_hhi[SB * Hh];
__device__ __nv_bfloat16 d_hlo[SB * Hh];
__device__ __nv_bfloat16 d_dinhi[SB * Hh];
__device__ __nv_bfloat16 d_dinlo[SB * Hh];
__device__ __nv_bfloat16 d_xhi[TENC * Bb * Hh];
__device__ __nv_bfloat16 d_xlo[TENC * Bb * Hh];
__device__ __nv_bfloat16 d_wfhi[H3 * Hh], d_wflo[H3 * Hh];
__device__ __nv_bfloat16 d_wbhi[H3 * Hh], d_wblo[H3 * Hh];
__device__ __nv_bfloat16 d_wihi[H3 * Hh], d_wilo[H3 * Hh];
__device__ __nv_bfloat16 d_whhi[H3 * Hh], d_whlo[H3 * Hh];

// ---------------- packed f32x2 helpers ----------------
__device__ __forceinline__ ull pack2(float x, float y) {
    ull r; asm("mov.b64 %0, {%1, %2};" : "=l"(r) : "f"(x), "f"(y)); return r;
}
__device__ __forceinline__ void unpack2(ull v, float& x, float& y) {
    asm("mov.b64 {%0, %1}, %2;" : "=f"(x), "=f"(y) : "l"(v));
}
__device__ __forceinline__ void ffma2(ull& d, ull a, ull b) {
    asm("fma.rn.f32x2 %0, %1, %2, %3;" : "=l"(d) : "l"(a), "l"(b), "l"(d));
}

// ---------------- fast exp ----------------
__device__ __forceinline__ float fexp(float x) {
    x = fminf(fmaxf(x, -80.0f), 80.0f);
    float y = x * 1.4426950408889634f;
    int   i = __float2int_rn(y);
    float f = y - (float)i;
    float u = f * 0.6931471805599453f;
    float p = 1.0f + u * (1.0f + u * (0.5f + u * (0.16666667f +
              u * (0.041666668f + u * (0.008333334f + u * 0.0013888889f)))));
    return __int_as_float(__float_as_int(p) + (i << 23));
}
__device__ __forceinline__ float fsig(float x) { return 1.0f / (1.0f + fexp(-x)); }

__device__ __forceinline__ void bsplit(float v, __nv_bfloat16& hi, __nv_bfloat16& lo) {
    hi = __float2bfloat16(v);
    lo = __float2bfloat16(v - __bfloat162float(hi));
}

// ---------------- mma / ldmatrix ----------------
__device__ __forceinline__ void mma_bf16(float* c, const u32* a, const u32* b) {
    asm volatile(
        "mma.sync.aligned.m16n8k16.row.col.f32.bf16.bf16.f32 "
        "{%0,%1,%2,%3}, {%4,%5,%6,%7}, {%8,%9}, {%0,%1,%2,%3};"
        : "+f"(c[0]), "+f"(c[1]), "+f"(c[2]), "+f"(c[3])
        : "r"(a[0]), "r"(a[1]), "r"(a[2]), "r"(a[3]), "r"(b[0]), "r"(b[1]));
}
__device__ __forceinline__ void ldsm_x4(u32& r0, u32& r1, u32& r2, u32& r3, u32 addr) {
    asm volatile("ldmatrix.sync.aligned.m8n8.x4.shared.b16 {%0,%1,%2,%3}, [%4];"
        : "=r"(r0), "=r"(r1), "=r"(r2), "=r"(r3) : "r"(addr));
}

// ---------------- init ----------------
__global__ void k_init() {
    int tid = blockIdx.x * blockDim.x + threadIdx.x;
    if (tid == 0) {
        g_barcnt[0] = 0u; g_barcnt[1] = 0u;
        g_bargen[0] = 0u; g_bargen[1] = 0u;
    }
    for (int i = tid; i < 2 * 2 * Bb * Hh; i += gridDim.x * blockDim.x)
        ((float*)d_Hbuf)[i] = 0.0f;
}

// ---------------- one-time conversions ----------------
__global__ void k_embconv(const float* __restrict__ emb) {
    long idx = (long)blockIdx.x * blockDim.x + threadIdx.x;
    if (idx >= (long)Vv * Hh) return;
    bsplit(emb[idx], d_ehi[idx], d_elo[idx]);
}
__global__ void k_wsplit(const float* __restrict__ w, __nv_bfloat16* hi, __nv_bfloat16* lo, int n) {
    int idx = blockIdx.x * blockDim.x + threadIdx.x;
    if (idx >= n) return;
    bsplit(w[idx], hi[idx], lo[idx]);
}
__global__ void k_embed(const int* __restrict__ story) {
    long idx = (long)blockIdx.x * blockDim.x + threadIdx.x;
    if (idx >= (long)TENC * Bb * Hh) return;
    int h = (int)(idx % Hh);
    int tb = (int)(idx / Hh);
    int b = tb & 15, t = tb >> 4;
    long src = (long)story[b * TENC + t] * Hh + h;
    d_xhi[idx] = d_ehi[src];
    d_xlo[idx] = d_elo[src];
}

// ---------------- generic batched TN SGEMM (64x64x16) — attention only ----------------
__global__ void __launch_bounds__(256) k_sgemm(
    const float* __restrict__ A, int lda, long sA,
    const float* __restrict__ Bw, int ldb, long sB,
    const float* __restrict__ bias,
    float* __restrict__ C, int ldc, long sC,
    int M, int N, int K)
{
    A  += (long)blockIdx.z * sA;
    Bw += (long)blockIdx.z * sB;
    C  += (long)blockIdx.z * sC;
    __shared__ float As[16][68];
    __shared__ float Bs[16][68];
    int tid = threadIdx.x;
    int tx = tid & 15, ty = tid >> 4;
    int row0 = blockIdx.y * 64, col0 = blockIdx.x * 64;
    int lm = tid >> 2, lk = (tid & 3) << 2;
    float acc[4][4] = {{0.f}};

    for (int k0 = 0; k0 < K; k0 += 16) {
        float4 va = make_float4(0.f, 0.f, 0.f, 0.f);
        float4 vb = make_float4(0.f, 0.f, 0.f, 0.f);
        if (row0 + lm < M) va = *(const float4*)(A + (long)(row0 + lm) * lda + k0 + lk);
        if (col0 + lm < N) vb = *(const float4*)(Bw + (long)(col0 + lm) * ldb + k0 + lk);
        __syncthreads();
        As[lk][lm] = va.x; As[lk+1][lm] = va.y; As[lk+2][lm] = va.z; As[lk+3][lm] = va.w;
        Bs[lk][lm] = vb.x; Bs[lk+1][lm] = vb.y; Bs[lk+2][lm] = vb.z; Bs[lk+3][lm] = vb.w;
        __syncthreads();
#pragma unroll
        for (int kk = 0; kk < 16; kk++) {
            float4 a = *(const float4*)&As[kk][ty << 2];
            float4 b = *(const float4*)&Bs[kk][tx << 2];
            acc[0][0] += a.x*b.x; acc[0][1] += a.x*b.y; acc[0][2] += a.x*b.z; acc[0][3] += a.x*b.w;
            acc[1][0] += a.y*b.x; acc[1][1] += a.y*b.y; acc[1][2] += a.y*b.z; acc[1][3] += a.y*b.w;
            acc[2][0] += a.z*b.x; acc[2][1] += a.z*b.y; acc[2][2] += a.z*b.z; acc[2][3] += a.z*b.w;
            acc[3][0] += a.w*b.x; acc[3][1] += a.w*b.y; acc[3][2] += a.w*b.z; acc[3][3] += a.w*b.w;
        }
    }
#pragma unroll
    for (int i = 0; i < 4; i++) {
        int gm = row0 + (ty << 2) + i;
        if (gm >= M) continue;
#pragma unroll
        for (int j = 0; j < 4; j++) {
            int gn = col0 + (tx << 2) + j;
            if (gn >= N) continue;
            float v = acc[i][j];
            if (bias) v += __ldg(&bias[gn]);
            C[(long)gm * ldc + gn] = v;
        }
    }
}

// ---------------- 128x128 split-bf16 tensor-core GEMM (ldmatrix fragments) ----------------
__global__ void __launch_bounds__(256) k_mma128(
    const __nv_bfloat16* __restrict__ Ahi, const __nv_bfloat16* __restrict__ Alo,
    const __nv_bfloat16* __restrict__ Bhi, const __nv_bfloat16* __restrict__ Blo,
    const float* __restrict__ bias,
    float* __restrict__ C, long ldc,
    float* __restrict__ rowsum, int expmode,
    int M, int N, int K)
{
    __shared__ __nv_bfloat16 As[2][128][24];
    __shared__ __nv_bfloat16 Bs[2][128][24];
    int tid = threadIdx.x;
    int warp = tid >> 5, lane = tid & 31;
    int wm = warp >> 1, wn = warp & 1;
    int g = lane >> 2, tig = lane & 3;
    int m0 = blockIdx.y * 128, n0 = blockIdx.x * 128;

    u32 aA0 = (u32)__cvta_generic_to_shared(&As[0][0][0]);
    u32 aA1 = (u32)__cvta_generic_to_shared(&As[1][0][0]);
    u32 aB0 = (u32)__cvta_generic_to_shared(&Bs[0][0][0]);
    u32 aB1 = (u32)__cvta_generic_to_shared(&Bs[1][0][0]);
    int arowA = (lane & 15);
    int acolA = (lane >> 4) * 8;
    int arowB = (lane & 7) + ((lane >> 4) << 3);
    int acolB = ((lane >> 3) & 1) * 8;
    u32 offA[2], offB[4];
#pragma unroll
    for (int mt = 0; mt < 2; mt++)
        offA[mt] = (u32)(((wm * 32 + mt * 16 + arowA) * 24 + acolA) * 2);
#pragma unroll
    for (int sp = 0; sp < 4; sp++)
        offB[sp] = (u32)(((wn * 64 + sp * 16 + arowB) * 24 + acolB) * 2);

    float c[2][8][4];
#pragma unroll
    for (int mt = 0; mt < 2; mt++)
#pragma unroll
        for (int s = 0; s < 8; s++)
#pragma unroll
            for (int q = 0; q < 4; q++) c[mt][s][q] = 0.f;

    for (int kc = 0; kc < K; kc += 16) {
        __syncthreads();
#pragma unroll
        for (int it = 0; it < 4; it++) {
            int idx = it * 256 + tid;
            int row = idx >> 3, pr = idx & 7;
            {
                int gm = m0 + row;
                u32 vh = 0u, vl = 0u;
                if (gm < M) {
                    long gi = (long)gm * K + kc + pr * 2;
                    vh = *(const u32*)(Ahi + gi);
                    vl = *(const u32*)(Alo + gi);
                }
                *(u32*)&As[0][row][pr * 2] = vh;
                *(u32*)&As[1][row][pr * 2] = vl;
            }
            {
                int gn = n0 + row;
                u32 vh = 0u, vl = 0u;
                if (gn < N) {
                    long gi = (long)gn * K + kc + pr * 2;
                    vh = *(const u32*)(Bhi + gi);
                    vl = *(const u32*)(Blo + gi);
                }
                *(u32*)&Bs[0][row][pr * 2] = vh;
                *(u32*)&Bs[1][row][pr * 2] = vl;
            }
        }
        __syncthreads();

        u32 ah[2][4], al[2][4];
#pragma unroll
        for (int mt = 0; mt < 2; mt++) {
            ldsm_x4(ah[mt][0], ah[mt][1], ah[mt][2], ah[mt][3], aA0 + offA[mt]);
            ldsm_x4(al[mt][0], al[mt][1], al[mt][2], al[mt][3], aA1 + offA[mt]);
        }
#pragma unroll
        for (int sp = 0; sp < 4; sp++) {
            u32 bh[4], bl[4];
            ldsm_x4(bh[0], bh[1], bh[2], bh[3], aB0 + offB[sp]);
            ldsm_x4(bl[0], bl[1], bl[2], bl[3], aB1 + offB[sp]);
#pragma unroll
            for (int half = 0; half < 2; half++) {
                int sub = sp * 2 + half;
#pragma unroll
                for (int mt = 0; mt < 2; mt++) {
                    mma_bf16(c[mt][sub], ah[mt], bh + half * 2);
                    mma_bf16(c[mt][sub], ah[mt], bl + half * 2);
                    mma_bf16(c[mt][sub], al[mt], bh + half * 2);
                }
            }
        }
    }

#pragma unroll
    for (int mt = 0; mt < 2; mt++) {
        int gmA = m0 + wm * 32 + mt * 16 + g;
        int gmB = gmA + 8;
        float sA = 0.f, sB = 0.f;
#pragma unroll
        for (int sub = 0; sub < 8; sub++) {
            int gn = n0 + wn * 64 + sub * 8 + tig * 2;
            if (gn < N) {
                float v0 = c[mt][sub][0], v1 = c[mt][sub][1];
                float v2 = c[mt][sub][2], v3 = c[mt][sub][3];
                if (bias) {
                    float b0 = __ldg(&bias[gn]), b1 = __ldg(&bias[gn + 1]);
                    v0 += b0; v1 += b1; v2 += b0; v3 += b1;
                }
                if (expmode) { v0 = fexp(v0); v1 = fexp(v1); v2 = fexp(v2); v3 = fexp(v3); }
                if (gmA < M) *(float2*)(C + (long)gmA * ldc + gn) = make_float2(v0, v1);
                if (gmB < M) *(float2*)(C + (long)gmB * ldc + gn) = make_float2(v2, v3);
                sA += v0 + v1; sB += v2 + v3;
            }
        }
        if (rowsum) {
            sA += __shfl_xor_sync(0xffffffffu, sA, 1);
            sA += __shfl_xor_sync(0xffffffffu, sA, 2);
            sB += __shfl_xor_sync(0xffffffffu, sB, 1);
            sB += __shfl_xor_sync(0xffffffffu, sB, 2);
            if (tig == 0) {
                if (gmA < M) atomicAdd(rowsum + gmA, sA);
                if (gmB < M) atomicAdd(rowsum + gmB, sB);
            }
        }
    }
}

// ---------------- decoder GRU GEMMs on tensor cores ----------------
// z=0: GI = din@dWi^T + bi ; z=1: GH = h@dWh^T + bh. M=SB, N=H3, K=Hh.
__global__ void __launch_bounds__(256) k_mmadec(
    const float* __restrict__ dbi, const float* __restrict__ dbh)
{
    const __nv_bfloat16* Ahi = blockIdx.z ? d_hhi : d_dinhi;
    const __nv_bfloat16* Alo = blockIdx.z ? d_hlo : d_dinlo;
    const __nv_bfloat16* Bhi = blockIdx.z ? d_whhi : d_wihi;
    const __nv_bfloat16* Blo = blockIdx.z ? d_whlo : d_wilo;
    const float* bias = blockIdx.z ? dbh : dbi;
    float* C = d_S + (blockIdx.z ? OGH : OGI);

    __shared__ __nv_bfloat16 As[2][128][24];
    __shared__ __nv_bfloat16 Bs[2][128][24];
    int tid = threadIdx.x;
    int warp = tid >> 5, lane = tid & 31;
    int wm = warp >> 1, wn = warp & 1;
    int g = lane >> 2, tig = lane & 3;
    int m0 = blockIdx.y * 128, n0 = blockIdx.x * 128;

    u32 aA0 = (u32)__cvta_generic_to_shared(&As[0][0][0]);
    u32 aA1 = (u32)__cvta_generic_to_shared(&As[1][0][0]);
    u32 aB0 = (u32)__cvta_generic_to_shared(&Bs[0][0][0]);
    u32 aB1 = (u32)__cvta_generic_to_shared(&Bs[1][0][0]);
    int arowA = (lane & 15);
    int acolA = (lane >> 4) * 8;
    int arowB = (lane & 7) + ((lane >> 4) << 3);
    int acolB = ((lane >> 3) & 1) * 8;
    u32 offA[2], offB[4];
#pragma unroll
    for (int mt = 0; mt < 2; mt++)
        offA[mt] = (u32)(((wm * 32 + mt * 16 + arowA) * 24 + acolA) * 2);
#pragma unroll
    for (int sp = 0; sp < 4; sp++)
        offB[sp] = (u32)(((wn * 64 + sp * 16 + arowB) * 24 + acolB) * 2);

    float c[2][8][4];
#pragma unroll
    for (int mt = 0; mt < 2; mt++)
#pragma unroll
        for (int s = 0; s < 8; s++)
#pragma unroll
            for (int q = 0; q < 4; q++) c[mt][s][q] = 0.f;

    for (int kc = 0; kc < Hh; kc += 16) {
        __syncthreads();
#pragma unroll
        for (int it = 0; it < 4; it++) {
            int idx = it * 256 + tid;
            int row = idx >> 3, pr = idx & 7;
            {
                int gm = m0 + row;
                u32 vh = 0u, vl = 0u;
                if (gm < SB) {
                    long gi = (long)gm * Hh + kc + pr * 2;
                    vh = *(const u32*)(Ahi + gi);
                    vl = *(const u32*)(Alo + gi);
                }
                *(u32*)&As[0][row][pr * 2] = vh;
                *(u32*)&As[1][row][pr * 2] = vl;
            }
            {
                int gn = n0 + row;
                u32 vh = 0u, vl = 0u;
                if (gn < H3) {
                    long gi = (long)gn * Hh + kc + pr * 2;
                    vh = *(const u32*)(Bhi + gi);
                    vl = *(const u32*)(Blo + gi);
                }
                *(u32*)&Bs[0][row][pr * 2] = vh;
                *(u32*)&Bs[1][row][pr * 2] = vl;
            }
        }
        __syncthreads();

        u32 ah[2][4], al[2][4];
#pragma unroll
        for (int mt = 0; mt < 2; mt++) {
            ldsm_x4(ah[mt][0], ah[mt][1], ah[mt][2], ah[mt][3], aA0 + offA[mt]);
            ldsm_x4(al[mt][0], al[mt][1], al[mt][2], al[mt][3], aA1 + offA[mt]);
        }
#pragma unroll
        for (int sp = 0; sp < 4; sp++) {
            u32 bh[4], bl[4];
            ldsm_x4(bh[0], bh[1], bh[2], bh[3], aB0 + offB[sp]);
            ldsm_x4(bl[0], bl[1], bl[2], bl[3], aB1 + offB[sp]);
#pragma unroll
            for (int half = 0; half < 2; half++) {
                int sub = sp * 2 + half;
#pragma unroll
                for (int mt = 0; mt < 2; mt++) {
                    mma_bf16(c[mt][sub], ah[mt], bh + half * 2);
                    mma_bf16(c[mt][sub], ah[mt], bl + half * 2);
                    mma_bf16(c[mt][sub], al[mt], bh + half * 2);
                }
            }
        }
    }

#pragma unroll
    for (int mt = 0; mt < 2; mt++) {
        int gmA = m0 + wm * 32 + mt * 16 + g;
        int gmB = gmA + 8;
#pragma unroll
        for (int sub = 0; sub < 8; sub++) {
            int gn = n0 + wn * 64 + sub * 8 + tig * 2;
            if (gn < H3) {
                float b0 = __ldg(&bias[gn]), b1 = __ldg(&bias[gn + 1]);
                if (gmA < SB) *(float2*)(C + (long)gmA * H3 + gn)
                    = make_float2(c[mt][sub][0] + b0, c[mt][sub][1] + b1);
                if (gmB < SB) *(float2*)(C + (long)gmB * H3 + gn)
                    = make_float2(c[mt][sub][2] + b0, c[mt][sub][3] + b1);
            }
        }
    }
}

// ---------------- persistent bi-GRU encoder (unchanged from R12) ----------------
__global__ void __launch_bounds__(384, 1) k_enc(
    const float* __restrict__ Whh_f, const float* __restrict__ Whh_b,
    const float* __restrict__ bhh_f, const float* __restrict__ bhh_b)
{
    __shared__ float hs[16 * 404];
    __shared__ float ghs[24 * 16];
    __shared__ float bsh[24];

    int dir = (int)(blockIdx.x / 50);
    int jb  = (int)(blockIdx.x % 50);
    int j0  = jb * 8;
    const float* Whh = dir ? Whh_b : Whh_f;
    const float* bhh = dir ? bhh_b : bhh_f;
    const float* GI  = d_S + (dir ? OGI1 : OGI0);
    float* OUT = d_S + (dir ? OHB : OHF);
    unsigned* cntp = &g_barcnt[dir];
    unsigned* genp = &g_bargen[dir];
    int tid = threadIdx.x;

    int kp = tid & 15;
    int rgi = (tid >> 4) & 3;
    int qg = tid >> 6;
    int kbase = kp * 25;

    if (tid < 24) { int gate = tid >> 3, jl = tid & 7; bsh[tid] = bhh[gate * 400 + j0 + jl]; }

    ull  Wp[4][12];
    float Wlast[4];
#pragma unroll
    for (int i = 0; i < 4; i++) {
        int q = qg * 4 + i;
        int gate = q >> 3, jl = q & 7;
        const float* wr = Whh + (long)(gate * 400 + j0 + jl) * 400 + kbase;
#pragma unroll
        for (int kk = 0; kk < 12; kk++) Wp[i][kk] = pack2(wr[2 * kk], wr[2 * kk + 1]);
        Wlast[i] = wr[24];
    }
    __syncthreads();

    for (int t = 0; t < TENC; ++t) {
        int p = t & 1;
        const float4* Hin4 = (const float4*)d_Hbuf[dir][p];
        float* Hout = d_Hbuf[dir][p ^ 1];

        float ir = 0.f, iz = 0.f, ig = 0.f;
        int time = dir ? (TENC - 1 - t) : t;
        if (tid < 128) {
            int rr = tid & 15, jj = tid >> 4;
            long gib = ((long)time * Bb + rr) * H3 + j0 + jj;
            ir = GI[gib]; iz = GI[gib + 400]; ig = GI[gib + 800];
        }

        for (int i4 = tid; i4 < 1600; i4 += 384) {
            float4 v = __ldcg(Hin4 + i4);
            int row = i4 / 100, c4 = (i4 % 100) << 2;
            *(float4*)&hs[row * 404 + c4] = v;
        }
        __syncthreads();

        ull acc2[4][4];
        float accl[4][4];
#pragma unroll
        for (int i = 0; i < 4; i++)
#pragma unroll
            for (int j = 0; j < 4; j++) { acc2[i][j] = 0ULL; accl[i][j] = 0.f; }

        const float* h0 = hs + (rgi * 4 + 0) * 404 + kbase;
        const float* h1 = hs + (rgi * 4 + 1) * 404 + kbase;
        const float* h2 = hs + (rgi * 4 + 2) * 404 + kbase;
        const float* h3 = hs + (rgi * 4 + 3) * 404 + kbase;
#pragma unroll
        for (int kk = 0; kk < 12; kk++) {
            ull hp0 = pack2(h0[2 * kk], h0[2 * kk + 1]);
            ull hp1 = pack2(h1[2 * kk], h1[2 * kk + 1]);
            ull hp2 = pack2(h2[2 * kk], h2[2 * kk + 1]);
            ull hp3 = pack2(h3[2 * kk], h3[2 * kk + 1]);
#pragma unroll
            for (int i = 0; i < 4; i++) {
                ull w = Wp[i][kk];
                ffma2(acc2[i][0], w, hp0);
                ffma2(acc2[i][1], w, hp1);
                ffma2(acc2[i][2], w, hp2);
                ffma2(acc2[i][3], w, hp3);
            }
        }
        {
            float hv0 = h0[24], hv1 = h1[24], hv2 = h2[24], hv3 = h3[24];
#pragma unroll
            for (int i = 0; i < 4; i++) {
                accl[i][0] += Wlast[i] * hv0;
                accl[i][1] += Wlast[i] * hv1;
                accl[i][2] += Wlast[i] * hv2;
                accl[i][3] += Wlast[i] * hv3;
            }
        }

#pragma unroll
        for (int i = 0; i < 4; i++)
#pragma unroll
            for (int j = 0; j < 4; j++) {
                float lo, hi;
                unpack2(acc2[i][j], lo, hi);
                float v = lo + hi + accl[i][j];
                v += __shfl_xor_sync(0xffffffffu, v, 1);
                v += __shfl_xor_sync(0xffffffffu, v, 2);
                v += __shfl_xor_sync(0xffffffffu, v, 4);
                v += __shfl_xor_sync(0xffffffffu, v, 8);
                accl[i][j] = v;
            }
        if (kp == 0) {
#pragma unroll
            for (int i = 0; i < 4; i++) {
                float bb = bsh[qg * 4 + i];
#pragma unroll
                for (int j = 0; j < 4; j++)
                    ghs[(qg * 4 + i) * 16 + (rgi * 4 + j)] = accl[i][j] + bb;
            }
        }
        __syncthreads();

        float hn = 0.f;
        int rr = tid & 15, jj = tid >> 4;
        if (tid < 128) {
            float hr_ = ghs[jj * 16 + rr];
            float hz_ = ghs[(8 + jj) * 16 + rr];
            float hg_ = ghs[(16 + jj) * 16 + rr];
            float hp  = hs[rr * 404 + j0 + jj];
            float rg_ = fsig(ir + hr_);
            float zg = fsig(iz + hz_);
            float gg = tanhf(ig + rg_ * hg_);
            hn = (1.f - zg) * gg + zg * hp;
            Hout[rr * 400 + j0 + jj] = hn;
        }
        __syncthreads();
        if (tid == 0) {
            unsigned a;
            asm volatile("atom.acq_rel.gpu.add.u32 %0, [%1], 1;"
                         : "=r"(a) : "l"(cntp) : "memory");
            if (a == 50u * (unsigned)(t + 1) - 1u) {
                asm volatile("red.release.gpu.add.u32 [%0], 1;" :: "l"(genp) : "memory");
            } else {
                unsigned gv;
                while (1) {
                    asm volatile("ld.acquire.gpu.u32 %0, [%1];" : "=r"(gv) : "l"(genp) : "memory");
                    if (gv >= (unsigned)(t + 1)) break;
                    __nanosleep(16);
                }
            }
        }
        if (tid < 128)
            OUT[((long)time * Bb + rr) * Hh + j0 + jj] = hn;
        __syncthreads();
    }
}

// ---------------- enc_out (B,T,H) and its transpose (B,H,T) ----------------
__global__ void k_encout() {
    long idx = (long)blockIdx.x * blockDim.x + threadIdx.x;
    if (idx >= (long)Bb * TENC * Hh) return;
    int b = (int)(idx / (TENC * Hh));
    int rem = (int)(idx % (TENC * Hh));
    int t = rem / Hh, h = rem % Hh;
    long src = ((long)t * Bb + b) * Hh + h;
    float v = d_S[OHF + src] + d_S[OHB + src];
    d_S[OEO + idx] = v;
    d_S[OEOT + (long)b * (Hh * TENC) + (long)h * TENC + t] = v;
}

// ---------------- decoder init ----------------
__global__ void k_dec_init(const float* __restrict__ slot) {
    int idx = blockIdx.x * blockDim.x + threadIdx.x;
    if (idx >= SB * Hh) return;
    int n = idx / Hh, h = idx % Hh;
    int s = n >> 4, b = n & 15;
    float hv = d_S[OHF + ((long)(TENC - 1) * Bb + b) * Hh + h]
             + d_S[OHB + ((long)b) * Hh + h];
    float dv = slot[s * Hh + h];
    d_S[OH + idx] = hv;
    d_S[ODIN + idx] = dv;
    bsplit(hv, d_hhi[idx], d_hlo[idx]);
    bsplit(dv, d_dinhi[idx], d_dinlo[idx]);
}

// ---------------- decoder GRU gates; zero rowsum + bf16 split of h ----------------
__global__ void k_dec_gates() {
    int idx = blockIdx.x * blockDim.x + threadIdx.x;
    if (idx < SB) d_S[ORSUM + idx] = 0.f;
    if (idx >= SB * Hh) return;
    int n = idx / Hh, j = idx % Hh;
    long gb = (long)n * H3 + j;
    float ir = d_S[OGI + gb], iz = d_S[OGI + gb + 400], ig = d_S[OGI + gb + 800];
    float hr = d_S[OGH + gb], hz = d_S[OGH + gb + 400], hg = d_S[OGH + gb + 800];
    float hp = d_S[OH + idx];
    float r = fsig(ir + hr);
    float z = fsig(iz + hz);
    float g = tanhf(ig + r * hg);
    float hn = (1.f - z) * g + z * hp;
    d_S[OH + idx] = hn;
    bsplit(hn, d_hhi[idx], d_hlo[idx]);
}

// ---------------- attention softmax over T=256 ----------------
__global__ void k_softmax_att() {
    int n = blockIdx.x, tid = threadIdx.x;
    __shared__ float red[256];
    float x = d_S[OPROB + (long)n * TENC + tid];
    red[tid] = x; __syncthreads();
    for (int o = 128; o; o >>= 1) { if (tid < o) red[tid] = fmaxf(red[tid], red[tid + o]); __syncthreads(); }
    float m = red[0]; __syncthreads();
    float e = fexp(x - m);
    red[tid] = e; __syncthreads();
    for (int o = 128; o; o >>= 1) { if (tid < o) red[tid] += red[tid + o]; __syncthreads(); }
    d_S[OPROB + (long)n * TENC + tid] = e / red[0];
}

// ---------------- sw (p_gen ratio) and (t==0) gate outputs ----------------
__global__ void k_sw_gate(const float* __restrict__ Wr, const float* __restrict__ br,
                          const float* __restrict__ Wg, const float* __restrict__ bg,
                          float* __restrict__ out, int t) {
    int warp = (blockIdx.x * blockDim.x + threadIdx.x) >> 5;
    int lane = threadIdx.x & 31;
    if (warp >= SB) return;
    int n = warp;
    float s = 0.f;
    for (int j = lane; j < H3; j += 32) {
        float v = (j < 400) ? d_S[OH + (long)n * Hh + j]
                : (j < 800) ? d_S[OCTX + (long)n * Hh + j - 400]
                            : d_S[ODIN + (long)n * Hh + j - 800];
        s += v * Wr[j];
    }
    for (int o = 16; o; o >>= 1) s += __shfl_xor_sync(0xffffffffu, s, o);
    if (lane == 0) d_S[OSW + n] = fsig(s + br[0]);
    if (t == 0) {
        for (int g = 0; g < Gg; g++) {
            float a = 0.f;
            for (int j = lane; j < Hh; j += 32) a += d_S[OCTX + (long)n * Hh + j] * Wg[g * Hh + j];
            for (int o = 16; o; o >>= 1) a += __shfl_xor_sync(0xffffffffu, a, o);
            if (lane == 0) out[PTR_OUT + (long)n * Gg + g] = a + bg[g];
        }
    }
}

// ---------------- fused finalize: scale out, scatter pointer, next din (+splits) ----------------
__global__ void __launch_bounds__(256) k_finalize(
    float* __restrict__ out, const int* __restrict__ story,
    const int* __restrict__ tb, const float* __restrict__ emb, int t)
{
    int n = blockIdx.x, tid = threadIdx.x;
    int s = n >> 4, b = n & 15;
    float sc = d_S[OSW + n] / d_S[ORSUM + n];
    float* row = out + ((long)n * TDEC + t) * Vv;

    for (int i = tid; i < Vv / 4; i += 256) {
        float4 e = *(const float4*)(row + i * 4);
        e.x *= sc; e.y *= sc; e.z *= sc; e.w *= sc;
        *(float4*)(row + i * 4) = e;
    }
    __syncthreads();

    {
        int tok = story[b * TENC + tid];
        float v = (1.f - d_S[OSW + n]) * d_S[OPROB + (long)n * TENC + tid];
        atomicAdd(row + tok, v);
    }
    {
        int tok = tb[(b * Ss + s) * TDEC + t];
        for (int h = tid; h < Hh; h += 256) {
            long di = (long)n * Hh + h;
            long si = (long)tok * Hh + h;
            d_S[ODIN + di] = emb[si];
            d_dinhi[di] = d_ehi[si];      // exact bf16 split of emb (precomputed)
            d_dinlo[di] = d_elo[si];
        }
    }
}

// ---------------- host ----------------
extern "C" void kernel_launch(void* const* d_in, const int* in_sizes, int n_in,
                              void* d_out, int out_size) {
    const int*   story = (const int*)d_in[0];
    const int*   tb    = (const int*)d_in[1];
    const float* emb   = (const float*)d_in[2];
    const float* eWif  = (const float*)d_in[3];
    const float* eWhf  = (const float*)d_in[4];
    const float* ebif  = (const float*)d_in[5];
    const float* ebhf  = (const float*)d_in[6];
    const float* eWib  = (const float*)d_in[7];
    const float* eWhb  = (const float*)d_in[8];
    const float* ebib  = (const float*)d_in[9];
    const float* ebhb  = (const float*)d_in[10];
    const float* dWi   = (const float*)d_in[11];
    const float* dWh   = (const float*)d_in[12];
    const float* dbi   = (const float*)d_in[13];
    const float* dbh   = (const float*)d_in[14];
    const float* Wr    = (const float*)d_in[15];
    const float* br    = (const float*)d_in[16];
    const float* Wg    = (const float*)d_in[17];
    const float* bg    = (const float*)d_in[18];
    const float* slot  = (const float*)d_in[19];
    float* out = (float*)d_out;

    float* S = nullptr;
    cudaGetSymbolAddress((void**)&S, d_S);
    float* pGI0  = S + OGI0;
    float* pGI1  = S + OGI1;
    float* pEO   = S + OEO;
    float* pEOT  = S + OEOT;
    float* pH    = S + OH;
    float* pPROB = S + OPROB;
    float* pCTX  = S + OCTX;
    float* pRS   = S + ORSUM;

    __nv_bfloat16 *xhi, *xlo, *wfhi, *wflo, *wbhi, *wblo, *ehi, *elo, *hhi, *hlo;
    __nv_bfloat16 *wihi, *wilo, *whhi, *whlo;
    cudaGetSymbolAddress((void**)&xhi, d_xhi);
    cudaGetSymbolAddress((void**)&xlo, d_xlo);
    cudaGetSymbolAddress((void**)&wfhi, d_wfhi);
    cudaGetSymbolAddress((void**)&wflo, d_wflo);
    cudaGetSymbolAddress((void**)&wbhi, d_wbhi);
    cudaGetSymbolAddress((void**)&wblo, d_wblo);
    cudaGetSymbolAddress((void**)&ehi, d_ehi);
    cudaGetSymbolAddress((void**)&elo, d_elo);
    cudaGetSymbolAddress((void**)&hhi, d_hhi);
    cudaGetSymbolAddress((void**)&hlo, d_hlo);
    cudaGetSymbolAddress((void**)&wihi, d_wihi);
    cudaGetSymbolAddress((void**)&wilo, d_wilo);
    cudaGetSymbolAddress((void**)&whhi, d_whhi);
    cudaGetSymbolAddress((void**)&whlo, d_whlo);

    k_init<<<32, 256>>>();
    k_embconv<<<(int)(((long)Vv * Hh + 255) / 256), 256>>>(emb);
    k_embed<<<(TENC * Bb * Hh + 255) / 256, 256>>>(story);
    k_wsplit<<<(H3 * Hh + 255) / 256, 256>>>(eWif, wfhi, wflo, H3 * Hh);
    k_wsplit<<<(H3 * Hh + 255) / 256, 256>>>(eWib, wbhi, wblo, H3 * Hh);
    k_wsplit<<<(H3 * Hh + 255) / 256, 256>>>(dWi, wihi, wilo, H3 * Hh);
    k_wsplit<<<(H3 * Hh + 255) / 256, 256>>>(dWh, whhi, whlo, H3 * Hh);

    // GI via tensor cores: (4096 x 1200 x 400)
    k_mma128<<<dim3(10, 32), 256>>>(xhi, xlo, wfhi, wflo, ebif, pGI0, H3, nullptr, 0, TENC * Bb, H3, Hh);
    k_mma128<<<dim3(10, 32), 256>>>(xhi, xlo, wbhi, wblo, ebib, pGI1, H3, nullptr, 0, TENC * Bb, H3, Hh);

    // persistent bidirectional GRU
    k_enc<<<100, 384>>>(eWhf, eWhb, ebhf, ebhb);

    k_encout<<<(Bb * TENC * Hh + 255) / 256, 256>>>();
    k_dec_init<<<(SB * Hh + 255) / 256, 256>>>(slot);

    for (int t = 0; t < TDEC; t++) {
        // decoder GRU GEMMs on tensor cores (z=0: GI, z=1: GH)
        k_mmadec<<<dim3(10, 4, 2), 256>>>(dbi, dbh);
        k_dec_gates<<<(SB * Hh + 255) / 256, 256>>>();

        k_sgemm<<<dim3(4, 1, Bb), 256>>>(pH, Bb * Hh, Hh, pEO, Hh, (long)TENC * Hh,
                                         nullptr, pPROB, Bb * TENC, TENC, Ss, TENC, Hh);
        k_softmax_att<<<SB, 256>>>();
        k_sgemm<<<dim3(7, 1, Bb), 256>>>(pPROB, Bb * TENC, TENC, pEOT, TENC, (long)Hh * TENC,
                                         nullptr, pCTX, Bb * Hh, Hh, Ss, Hh, TENC);

        k_sw_gate<<<60, 256>>>(Wr, br, Wg, bg, out, t);

        // tensor-core logits: exp(logit) straight into out + rowsum
        k_mma128<<<dim3(141, 4), 256>>>(hhi, hlo, ehi, elo, nullptr,
                                        out + (long)t * Vv, (long)TDEC * Vv, pRS, 1, SB, Vv, Hh);

        k_finalize<<<SB, 256>>>(out, story, tb, emb, t);
    }
}